// round 11
// baseline (speedup 1.0000x reference)
#include <cuda_runtime.h>
#include <cuda_bf16.h>
#include <math.h>
#include <stdint.h>

#define B_  4
#define S_  2048
#define D_  1024
#define H_  16
#define HD_ 64
#define M_  (B_*S_)

typedef __nv_bfloat16 bf16;

// ---------------- scratch ----------------
__device__ bf16 g_xh[(size_t)M_*D_];
__device__ bf16 g_xl[(size_t)M_*D_];
__device__ bf16 g_wh[(size_t)4*D_*D_];
__device__ bf16 g_wl[(size_t)4*D_*D_];
__device__ bf16 g_qh[(size_t)M_*D_];
__device__ bf16 g_ql[(size_t)M_*D_];
__device__ bf16 g_kh[(size_t)M_*D_];
__device__ bf16 g_kl[(size_t)M_*D_];
__device__ bf16 g_vh[(size_t)M_*D_];
__device__ bf16 g_vl[(size_t)M_*D_];

// ---------------- asm helpers ----------------
__device__ __forceinline__ uint32_t smem_u32(const void* p) {
    uint32_t a;
    asm("{ .reg .u64 t; cvta.to.shared.u64 t, %1; cvt.u32.u64 %0, t; }" : "=r"(a) : "l"(p));
    return a;
}
#define CP_ASYNC16(dst, src) \
    asm volatile("cp.async.cg.shared.global [%0], [%1], 16;" :: "r"(dst), "l"(src))
#define CP_COMMIT() asm volatile("cp.async.commit_group;" ::: "memory")
#define CP_WAIT(n)  asm volatile("cp.async.wait_group %0;" :: "n"(n) : "memory")

#define MMA_BF16(c, a, b0, b1) \
    asm volatile("mma.sync.aligned.m16n8k16.row.col.f32.bf16.bf16.f32 " \
        "{%0,%1,%2,%3}, {%4,%5,%6,%7}, {%8,%9}, {%0,%1,%2,%3};" \
        : "+f"((c)[0]), "+f"((c)[1]), "+f"((c)[2]), "+f"((c)[3]) \
        : "r"((a)[0]), "r"((a)[1]), "r"((a)[2]), "r"((a)[3]), "r"(b0), "r"(b1))

#define LDSM_X4(r0,r1,r2,r3, a) \
    asm volatile("ldmatrix.sync.aligned.m8n8.x4.shared.b16 {%0,%1,%2,%3}, [%4];" \
        : "=r"(r0), "=r"(r1), "=r"(r2), "=r"(r3) : "r"(a))

#define LDSM_X4_T(r0,r1,r2,r3, a) \
    asm volatile("ldmatrix.sync.aligned.m8n8.x4.trans.shared.b16 {%0,%1,%2,%3}, [%4];" \
        : "=r"(r0), "=r"(r1), "=r"(r2), "=r"(r3) : "r"(a))

__device__ __forceinline__ uint32_t pack_bf16(float lo, float hi) {
    __nv_bfloat162 t = __floats2bfloat162_rn(lo, hi);
    return *reinterpret_cast<uint32_t*>(&t);
}

// ---------------- fp32 -> bf16 hi/lo split ----------------
__global__ void split_kernel(const float* __restrict__ in, const int* __restrict__ mask,
                             bf16* __restrict__ hi, bf16* __restrict__ lo,
                             int n4, int use_mask)
{
    int i = blockIdx.x * blockDim.x + threadIdx.x;
    if (i >= n4) return;
    float4 v = reinterpret_cast<const float4*>(in)[i];
    if (use_mask) {
        float mv = (float)mask[i >> 8];
        v.x *= mv; v.y *= mv; v.z *= mv; v.w *= mv;
    }
    bf16 h0 = __float2bfloat16(v.x);
    bf16 h1 = __float2bfloat16(v.y);
    bf16 h2 = __float2bfloat16(v.z);
    bf16 h3 = __float2bfloat16(v.w);
    __nv_bfloat162 hh0; hh0.x = h0; hh0.y = h1;
    __nv_bfloat162 hh1; hh1.x = h2; hh1.y = h3;
    __nv_bfloat162 ll0, ll1;
    ll0.x = __float2bfloat16(v.x - __bfloat162float(h0));
    ll0.y = __float2bfloat16(v.y - __bfloat162float(h1));
    ll1.x = __float2bfloat16(v.z - __bfloat162float(h2));
    ll1.y = __float2bfloat16(v.w - __bfloat162float(h3));
    reinterpret_cast<__nv_bfloat162*>(hi)[2*i]   = hh0;
    reinterpret_cast<__nv_bfloat162*>(hi)[2*i+1] = hh1;
    reinterpret_cast<__nv_bfloat162*>(lo)[2*i]   = ll0;
    reinterpret_cast<__nv_bfloat162*>(lo)[2*i+1] = ll1;
}

// merged weight split: grid.y selects which W
__global__ void split4_kernel(const float* __restrict__ W0, const float* __restrict__ W1,
                              const float* __restrict__ W2, const float* __restrict__ W3,
                              bf16* __restrict__ hi, bf16* __restrict__ lo, int n4)
{
    int i = blockIdx.x * blockDim.x + threadIdx.x;
    if (i >= n4) return;
    const int w = blockIdx.y;
    const float* in = (w == 0) ? W0 : (w == 1) ? W1 : (w == 2) ? W2 : W3;
    const size_t off = (size_t)w * n4;
    float4 v = reinterpret_cast<const float4*>(in)[i];
    bf16 h0 = __float2bfloat16(v.x);
    bf16 h1 = __float2bfloat16(v.y);
    bf16 h2 = __float2bfloat16(v.z);
    bf16 h3 = __float2bfloat16(v.w);
    __nv_bfloat162 hh0; hh0.x = h0; hh0.y = h1;
    __nv_bfloat162 hh1; hh1.x = h2; hh1.y = h3;
    __nv_bfloat162 ll0, ll1;
    ll0.x = __float2bfloat16(v.x - __bfloat162float(h0));
    ll0.y = __float2bfloat16(v.y - __bfloat162float(h1));
    ll1.x = __float2bfloat16(v.z - __bfloat162float(h2));
    ll1.y = __float2bfloat16(v.w - __bfloat162float(h3));
    reinterpret_cast<__nv_bfloat162*>(hi)[2*(off + i)]   = hh0;
    reinterpret_cast<__nv_bfloat162*>(hi)[2*(off + i)+1] = hh1;
    reinterpret_cast<__nv_bfloat162*>(lo)[2*(off + i)]   = ll0;
    reinterpret_cast<__nv_bfloat162*>(lo)[2*(off + i)+1] = ll1;
}

// ---------------- mma.sync split-bf16 GEMM (unchanged from R10) ----------------
#define GS_A  40
#define G_STAGE (4*128*GS_A)    // elems per stage = 20480 (40960 B)

__device__ __forceinline__ void gemm_issue(const bf16* const srcs[4], bf16* stage,
                                           int chunk, int tid)
{
#pragma unroll
    for (int it = 0; it < 8; it++) {
        int unit = tid + it*256;
        int mat = unit >> 9, rem = unit & 511;
        int row = rem >> 2,  g  = rem & 3;
        const bf16* src = srcs[mat] + (size_t)row*D_ + chunk*32 + g*8;
        uint32_t dst = smem_u32(stage + mat*128*GS_A + row*GS_A + g*8);
        CP_ASYNC16(dst, src);
    }
}

__device__ __forceinline__ void mgemm_main(
    const bf16* __restrict__ Ah, const bf16* __restrict__ Al,
    const bf16* __restrict__ Bh, const bf16* __restrict__ Bl,
    int m0, int n0, int tid, bf16* stg0, float acc[2][8][4])
{
    bf16* stg[2] = { stg0, stg0 + G_STAGE };
    const int lane = tid & 31;
    const int wid = tid >> 5;
    const int wr = wid >> 1;
    const int wc = wid & 1;

#pragma unroll
    for (int mt = 0; mt < 2; mt++)
#pragma unroll
        for (int n = 0; n < 8; n++)
#pragma unroll
            for (int c = 0; c < 4; c++) acc[mt][n][c] = 0.0f;

    const bf16* srcs[4] = { Ah + (size_t)m0*D_, Al + (size_t)m0*D_,
                            Bh + (size_t)n0*D_, Bl + (size_t)n0*D_ };

    gemm_issue(srcs, stg[0], 0, tid); CP_COMMIT();

    const int rowA = wr*32 + ((lane >> 3) & 1)*8 + (lane & 7);
    const int colA = (lane >> 4)*8;
    const int rowB = wc*64 + (lane >> 4)*8 + (lane & 7);
    const int colB = ((lane >> 3) & 1)*8;

    for (int chunk = 0; chunk < 32; chunk++) {
        CP_WAIT(0);
        __syncthreads();
        if (chunk + 1 < 32) {
            gemm_issue(srcs, stg[(chunk + 1) & 1], chunk + 1, tid);
            CP_COMMIT();
        }

        bf16* As_h = stg[chunk & 1];
        bf16* As_l = As_h + 128*GS_A;
        bf16* Bs_h = As_l + 128*GS_A;
        bf16* Bs_l = Bs_h + 128*GS_A;

#pragma unroll
        for (int kk = 0; kk < 2; kk++) {
            uint32_t ah[2][4], al[2][4];
#pragma unroll
            for (int mt = 0; mt < 2; mt++) {
                uint32_t a = smem_u32(As_h + (rowA + mt*16)*GS_A + kk*16 + colA);
                LDSM_X4(ah[mt][0], ah[mt][1], ah[mt][2], ah[mt][3], a);
                a = smem_u32(As_l + (rowA + mt*16)*GS_A + kk*16 + colA);
                LDSM_X4(al[mt][0], al[mt][1], al[mt][2], al[mt][3], a);
            }
#pragma unroll
            for (int n4 = 0; n4 < 4; n4++) {
                uint32_t bh0, bh1, bh2, bh3, bl0, bl1, bl2, bl3;
                uint32_t a = smem_u32(Bs_h + (rowB + n4*16)*GS_A + kk*16 + colB);
                LDSM_X4(bh0, bh1, bh2, bh3, a);
                a = smem_u32(Bs_l + (rowB + n4*16)*GS_A + kk*16 + colB);
                LDSM_X4(bl0, bl1, bl2, bl3, a);
#pragma unroll
                for (int mt = 0; mt < 2; mt++) {
                    MMA_BF16(acc[mt][2*n4],   ah[mt], bh0, bh1);
                    MMA_BF16(acc[mt][2*n4],   ah[mt], bl0, bl1);
                    MMA_BF16(acc[mt][2*n4],   al[mt], bh0, bh1);
                    MMA_BF16(acc[mt][2*n4+1], ah[mt], bh2, bh3);
                    MMA_BF16(acc[mt][2*n4+1], ah[mt], bl2, bl3);
                    MMA_BF16(acc[mt][2*n4+1], al[mt], bh2, bh3);
                }
            }
        }
    }
}

// merged QKV GEMM: grid.x = 24 (proj = bx>>3, ntile = bx&7); register epilogue
__global__ void __launch_bounds__(256, 2) mgemm_qkv_kernel(
    const bf16* __restrict__ Ah, const bf16* __restrict__ Al,
    const bf16* __restrict__ Wh, const bf16* __restrict__ Wl,
    const float* __restrict__ bq, const float* __restrict__ bk, const float* __restrict__ bv,
    bf16* __restrict__ qh, bf16* __restrict__ ql,
    bf16* __restrict__ kh, bf16* __restrict__ kl,
    bf16* __restrict__ vh, bf16* __restrict__ vl)
{
    extern __shared__ char smraw[];
    __shared__ float sbias[128];
    const int tid = threadIdx.x;
    const int lane = tid & 31;
    const int wid = tid >> 5;
    const int wr = wid >> 1;
    const int wc = wid & 1;
    const int proj = blockIdx.x >> 3;
    const int n0 = (blockIdx.x & 7) * 128;
    const int m0 = blockIdx.y * 128;
    const size_t WSZ = (size_t)D_ * D_;

    const float* bias = (proj == 0) ? bq : (proj == 1) ? bk : bv;
    bf16* Ch = (proj == 0) ? qh : (proj == 1) ? kh : vh;
    bf16* Cl = (proj == 0) ? ql : (proj == 1) ? kl : vl;
    if (tid < 128) sbias[tid] = bias[n0 + tid];

    float acc[2][8][4];
    mgemm_main(Ah, Al, Wh + proj*WSZ, Wl + proj*WSZ, m0, n0, tid, (bf16*)smraw, acc);

    const int cb = (lane & 3)*2;
    const int e_loc = wc*64 + cb;
    const int h = (n0 + wc*64) >> 6;
#pragma unroll
    for (int mt = 0; mt < 2; mt++) {
#pragma unroll
        for (int half = 0; half < 2; half++) {
            const int m = m0 + wr*32 + mt*16 + half*8 + (lane >> 2);
            const int b = m >> 11, s = m & 2047;
            const size_t base = (((size_t)(b*H_ + h))*S_ + s)*HD_;
#pragma unroll
            for (int n = 0; n < 8; n++) {
                float v0 = acc[mt][n][half*2]     + sbias[e_loc + n*8];
                float v1 = acc[mt][n][half*2 + 1] + sbias[e_loc + n*8 + 1];
                float h0 = __bfloat162float(__float2bfloat16(v0));
                float h1 = __bfloat162float(__float2bfloat16(v1));
                const size_t off = base + n*8 + cb;
                *reinterpret_cast<uint32_t*>(Ch + off) = pack_bf16(h0, h1);
                *reinterpret_cast<uint32_t*>(Cl + off) = pack_bf16(v0 - h0, v1 - h1);
            }
        }
    }
}

// O-projection GEMM (fp32 out * rowmask), register epilogue
__global__ void __launch_bounds__(256, 2) mgemm_o_kernel(
    const bf16* __restrict__ Ah, const bf16* __restrict__ Al,
    const bf16* __restrict__ Bh, const bf16* __restrict__ Bl,
    const float* __restrict__ bias, const int* __restrict__ mask,
    float* __restrict__ Cf)
{
    extern __shared__ char smraw[];
    __shared__ float sbias[128];
    const int tid = threadIdx.x;
    const int lane = tid & 31;
    const int wid = tid >> 5;
    const int wr = wid >> 1;
    const int wc = wid & 1;
    const int m0 = blockIdx.y * 128;
    const int n0 = blockIdx.x * 128;
    if (tid < 128) sbias[tid] = bias[n0 + tid];

    float acc[2][8][4];
    mgemm_main(Ah, Al, Bh, Bl, m0, n0, tid, (bf16*)smraw, acc);

    const int cb = (lane & 3)*2;
    const int e_loc = wc*64 + cb;
#pragma unroll
    for (int mt = 0; mt < 2; mt++) {
#pragma unroll
        for (int half = 0; half < 2; half++) {
            const int m = m0 + wr*32 + mt*16 + half*8 + (lane >> 2);
            const float maskv = (float)mask[m];
            float* outp = Cf + (size_t)m*D_ + n0;
#pragma unroll
            for (int n = 0; n < 8; n++) {
                float2 v;
                v.x = (acc[mt][n][half*2]     + sbias[e_loc + n*8])     * maskv;
                v.y = (acc[mt][n][half*2 + 1] + sbias[e_loc + n*8 + 1]) * maskv;
                *reinterpret_cast<float2*>(outp + e_loc + n*8) = v;
            }
        }
    }
}

// ---------------- mma.sync attention: 3-stage (Q aliased with stage2), ----------------
// one sync per key tile, batched exp, 2 CTAs/SM.
#define AS_B 72
#define A_KTILE (64*AS_B)                     // elems per 64x64 tile
#define A_TILES_B (4*A_KTILE*2)               // 4 tiles bytes = 36864
#define A_STAGE_B (A_TILES_B + 256)           // + 64 int mask slot = 37120
#define A_QTILE (128*AS_B)                    // 9216 elems (18432 B); Qh+Ql = 36864 B <= stage

__device__ __forceinline__ void attn_issue(const bf16* const srcs[4],
                                           const int* __restrict__ maskp,
                                           char* stage, int kb, int tid)
{
    bf16* st = (bf16*)stage;
#pragma unroll
    for (int it = 0; it < 8; it++) {
        int unit = tid + it*256;
        int mat = unit >> 9, rem = unit & 511;
        int row = rem >> 3, g = rem & 7;
        const bf16* src = srcs[mat] + (size_t)(kb + row)*HD_ + g*8;
        uint32_t dst = smem_u32(st + mat*A_KTILE + row*AS_B + g*8);
        CP_ASYNC16(dst, src);
    }
    if (tid < 16)
        CP_ASYNC16(smem_u32(stage + A_TILES_B + tid*16), maskp + kb + tid*4);
}

__global__ void __launch_bounds__(256, 2) mattn_kernel(const int* __restrict__ mask)
{
    extern __shared__ char smraw[];
    char* stg[3] = { smraw, smraw + A_STAGE_B, smraw + 2*A_STAGE_B };
    // Q tile aliases stage 2 (Q is consumed into registers before stage 2 is first written)
    bf16* Qh = (bf16*)stg[2];
    bf16* Ql = Qh + A_QTILE;

    const int tid  = threadIdx.x;
    const int lane = tid & 31;
    const int ti   = tid >> 5;
    const int bh = blockIdx.y;
    const int b  = bh >> 4, h = bh & 15;
    const int q0 = blockIdx.x << 7;

    const bf16* srcs[4] = {
        g_kh + (size_t)bh*S_*HD_, g_kl + (size_t)bh*S_*HD_,
        g_vh + (size_t)bh*S_*HD_, g_vl + (size_t)bh*S_*HD_
    };
    const int* maskp = mask + b*S_;

    attn_issue(srcs, maskp, stg[0], 0,  tid); CP_COMMIT();
    attn_issue(srcs, maskp, stg[1], 64, tid); CP_COMMIT();

    // load Q hi/lo into stage-2 area while cp.async flies
    const bf16* Qgh = g_qh + ((size_t)bh*S_ + q0)*HD_;
    const bf16* Qgl = g_ql + ((size_t)bh*S_ + q0)*HD_;
#pragma unroll
    for (int it = 0; it < 4; it++) {
        int unit = tid + it*256;
        int row = unit >> 3, c8 = unit & 7;
        *reinterpret_cast<uint4*>(Qh + row*AS_B + c8*8) =
            *reinterpret_cast<const uint4*>(Qgh + row*HD_ + c8*8);
        *reinterpret_cast<uint4*>(Ql + row*AS_B + c8*8) =
            *reinterpret_cast<const uint4*>(Qgl + row*HD_ + c8*8);
    }
    __syncthreads();   // Q visible to all

    uint32_t qfh[4][4], qfl[4][4];
    {
        const int rowQ = ti*16 + ((lane >> 3) & 1)*8 + (lane & 7);
        const int colQ = (lane >> 4)*8;
#pragma unroll
        for (int g = 0; g < 4; g++) {
            uint32_t a = smem_u32(Qh + rowQ*AS_B + g*16 + colQ);
            LDSM_X4(qfh[g][0], qfh[g][1], qfh[g][2], qfh[g][3], a);
            a = smem_u32(Ql + rowQ*AS_B + g*16 + colQ);
            LDSM_X4(qfl[g][0], qfl[g][1], qfl[g][2], qfl[g][3], a);
        }
    }
    __syncthreads();   // all warps done reading Q area -> stage 2 free for kt=2

    float oc[8][4];
#pragma unroll
    for (int n = 0; n < 8; n++)
#pragma unroll
        for (int c = 0; c < 4; c++) oc[n][c] = 0.0f;
    float lp0 = 0.0f, lp1 = 0.0f;

    const int rowK = (lane >> 4)*8 + (lane & 7);
    const int colK = ((lane >> 3) & 1)*8;
    const int rowV = ((lane >> 3) & 1)*8 + (lane & 7);
    const int colV = (lane >> 4)*8;
    const int cb   = (lane & 3)*2;

    for (int kt = 0; kt < 32; kt++) {
        if (kt < 31) { CP_WAIT(1); } else { CP_WAIT(0); }
        __syncthreads();   // stage kt visible; stage (kt+2)%3 drained
        if (kt + 2 < 32) {
            attn_issue(srcs, maskp, stg[(kt + 2) % 3], (kt + 2) << 6, tid);
            CP_COMMIT();
        }

        char* st = stg[kt % 3];
        bf16* Kh_s = (bf16*)st;
        bf16* Kl_s = Kh_s + A_KTILE;
        bf16* Vh_s = Kl_s + A_KTILE;
        bf16* Vl_s = Vh_s + A_KTILE;
        const int* kmi = (const int*)(st + A_TILES_B);

        // ---- S = Q K^T (3-pass) ----
        float sc[8][4];
#pragma unroll
        for (int n = 0; n < 8; n++)
#pragma unroll
            for (int c = 0; c < 4; c++) sc[n][c] = 0.0f;

#pragma unroll
        for (int g = 0; g < 4; g++) {
#pragma unroll
            for (int n2 = 0; n2 < 4; n2++) {
                uint32_t kh0, kh1, kh2, kh3, kl0, kl1, kl2, kl3;
                uint32_t a = smem_u32(Kh_s + (n2*16 + rowK)*AS_B + g*16 + colK);
                LDSM_X4(kh0, kh1, kh2, kh3, a);
                a = smem_u32(Kl_s + (n2*16 + rowK)*AS_B + g*16 + colK);
                LDSM_X4(kl0, kl1, kl2, kl3, a);
                MMA_BF16(sc[2*n2],   qfh[g], kh0, kh1);
                MMA_BF16(sc[2*n2],   qfh[g], kl0, kl1);
                MMA_BF16(sc[2*n2],   qfl[g], kh0, kh1);
                MMA_BF16(sc[2*n2+1], qfh[g], kh2, kh3);
                MMA_BF16(sc[2*n2+1], qfh[g], kl2, kl3);
                MMA_BF16(sc[2*n2+1], qfl[g], kh2, kh3);
            }
        }

        // ---- batched exp: all 32 elements first (MUFU latency overlapped) ----
#pragma unroll
        for (int n = 0; n < 8; n++) {
            const int colb = n*8 + cb;
            const float km0 = (float)kmi[colb];
            const float km1 = (float)kmi[colb + 1];
            float p0 = __expf(sc[n][0] * 0.125f) * km0;
            float p1 = __expf(sc[n][1] * 0.125f) * km1;
            float p2 = __expf(sc[n][2] * 0.125f) * km0;
            float p3 = __expf(sc[n][3] * 0.125f) * km1;
            lp0 += p0 + p1;
            lp1 += p2 + p3;
            sc[n][0] = p0; sc[n][1] = p1; sc[n][2] = p2; sc[n][3] = p3;
        }

        // ---- pack + PV per 16-key group ----
#pragma unroll
        for (int g = 0; g < 4; g++) {
            uint32_t pfh[4], pfl[4];
#pragma unroll
            for (int nn = 0; nn < 2; nn++) {
                const int n = 2*g + nn;
                float p0 = sc[n][0], p1 = sc[n][1], p2 = sc[n][2], p3 = sc[n][3];
                float h0 = __bfloat162float(__float2bfloat16(p0));
                float h1 = __bfloat162float(__float2bfloat16(p1));
                float h2 = __bfloat162float(__float2bfloat16(p2));
                float h3 = __bfloat162float(__float2bfloat16(p3));
                pfh[nn*2]     = pack_bf16(h0, h1);
                pfh[nn*2 + 1] = pack_bf16(h2, h3);
                pfl[nn*2]     = pack_bf16(p0 - h0, p1 - h1);
                pfl[nn*2 + 1] = pack_bf16(p2 - h2, p3 - h3);
            }
#pragma unroll
            for (int d2 = 0; d2 < 4; d2++) {
                uint32_t vh0, vh1, vh2, vh3, vl0, vl1, vl2, vl3;
                uint32_t a = smem_u32(Vh_s + (g*16 + rowV)*AS_B + d2*16 + colV);
                LDSM_X4_T(vh0, vh1, vh2, vh3, a);
                a = smem_u32(Vl_s + (g*16 + rowV)*AS_B + d2*16 + colV);
                LDSM_X4_T(vl0, vl1, vl2, vl3, a);
                MMA_BF16(oc[2*d2],   pfh, vh0, vh1);
                MMA_BF16(oc[2*d2],   pfh, vl0, vl1);
                MMA_BF16(oc[2*d2],   pfl, vh0, vh1);
                MMA_BF16(oc[2*d2+1], pfh, vh2, vh3);
                MMA_BF16(oc[2*d2+1], pfh, vl2, vl3);
                MMA_BF16(oc[2*d2+1], pfl, vh2, vh3);
            }
        }
    }

    lp0 += __shfl_xor_sync(0xffffffffu, lp0, 1);
    lp0 += __shfl_xor_sync(0xffffffffu, lp0, 2);
    lp1 += __shfl_xor_sync(0xffffffffu, lp1, 1);
    lp1 += __shfl_xor_sync(0xffffffffu, lp1, 2);
    const float inv0 = (lp0 > 0.f) ? (1.0f / lp0) : 0.f;
    const float inv1 = (lp1 > 0.f) ? (1.0f / lp1) : 0.f;

    const int row0 = q0 + ti*16 + (lane >> 2);
    const size_t base0 = ((size_t)(b*S_ + row0))*D_ + h*HD_ + cb;
    const size_t base1 = base0 + 8*(size_t)D_;
#pragma unroll
    for (int n = 0; n < 8; n++) {
        float v00 = oc[n][0]*inv0, v01 = oc[n][1]*inv0;
        float v10 = oc[n][2]*inv1, v11 = oc[n][3]*inv1;
        float h00 = __bfloat162float(__float2bfloat16(v00));
        float h01 = __bfloat162float(__float2bfloat16(v01));
        float h10 = __bfloat162float(__float2bfloat16(v10));
        float h11 = __bfloat162float(__float2bfloat16(v11));
        *reinterpret_cast<uint32_t*>(g_xh + base0 + n*8) = pack_bf16(h00, h01);
        *reinterpret_cast<uint32_t*>(g_xh + base1 + n*8) = pack_bf16(h10, h11);
        *reinterpret_cast<uint32_t*>(g_xl + base0 + n*8) = pack_bf16(v00 - h00, v01 - h01);
        *reinterpret_cast<uint32_t*>(g_xl + base1 + n*8) = pack_bf16(v10 - h10, v11 - h11);
    }
}

// ---------------- launch ----------------
extern "C" void kernel_launch(void* const* d_in, const int* in_sizes, int n_in,
                              void* d_out, int out_size)
{
    const float* hidden = (const float*)d_in[0];
    const int*   mask   = (const int*)d_in[1];
    const float* Wq = (const float*)d_in[2];
    const float* bq = (const float*)d_in[3];
    const float* Wk = (const float*)d_in[4];
    const float* bk = (const float*)d_in[5];
    const float* Wv = (const float*)d_in[6];
    const float* bv = (const float*)d_in[7];
    const float* Wo = (const float*)d_in[8];
    const float* bo = (const float*)d_in[9];
    float* out = (float*)d_out;

    bf16 *xh, *xl, *wh, *wl, *qh, *ql, *kh, *kl, *vh, *vl;
    cudaGetSymbolAddress((void**)&xh, g_xh);
    cudaGetSymbolAddress((void**)&xl, g_xl);
    cudaGetSymbolAddress((void**)&wh, g_wh);
    cudaGetSymbolAddress((void**)&wl, g_wl);
    cudaGetSymbolAddress((void**)&qh, g_qh);
    cudaGetSymbolAddress((void**)&ql, g_ql);
    cudaGetSymbolAddress((void**)&kh, g_kh);
    cudaGetSymbolAddress((void**)&kl, g_kl);
    cudaGetSymbolAddress((void**)&vh, g_vh);
    cudaGetSymbolAddress((void**)&vl, g_vl);

    const size_t WSZ = (size_t)D_ * D_;
    const int xn4 = (M_ * D_) / 4;
    const int wn4 = (D_ * D_) / 4;

    split_kernel<<<(xn4 + 255)/256, 256>>>(hidden, mask, xh, xl, xn4, 1);
    split4_kernel<<<dim3((wn4 + 255)/256, 4), 256>>>(Wq, Wk, Wv, Wo, wh, wl, wn4);

    const int gsmem = 2 * G_STAGE * (int)sizeof(bf16);   // 81920
    cudaFuncSetAttribute(mgemm_qkv_kernel, cudaFuncAttributeMaxDynamicSharedMemorySize, gsmem);
    cudaFuncSetAttribute(mgemm_o_kernel,   cudaFuncAttributeMaxDynamicSharedMemorySize, gsmem);

    mgemm_qkv_kernel<<<dim3(24, M_/128), 256, gsmem>>>(
        xh, xl, wh, wl, bq, bk, bv, qh, ql, kh, kl, vh, vl);

    const int asmem = 3 * A_STAGE_B;   // 111360 (Q aliased into stage 2)
    cudaFuncSetAttribute(mattn_kernel, cudaFuncAttributeMaxDynamicSharedMemorySize, asmem);
    mattn_kernel<<<dim3(S_/128, B_*H_), 256, asmem>>>(mask);

    mgemm_o_kernel<<<dim3(D_/128, M_/128), 256, gsmem>>>(
        xh, xl, wh + 3*WSZ, wl + 3*WSZ, bo, mask, out);
}

// round 12
// speedup vs baseline: 1.3954x; 1.3954x over previous
#include <cuda_runtime.h>
#include <cuda_bf16.h>
#include <cuda_fp16.h>
#include <math.h>
#include <stdint.h>

#define B_  4
#define S_  2048
#define D_  1024
#define H_  16
#define HD_ 64
#define M_  (B_*S_)

typedef __nv_bfloat16 bf16;

// ---------------- scratch ----------------
__device__ bf16 g_xh[(size_t)M_*D_];
__device__ bf16 g_xl[(size_t)M_*D_];
__device__ bf16 g_wh[(size_t)4*D_*D_];
__device__ bf16 g_wl[(size_t)4*D_*D_];
__device__ __half g_q[(size_t)M_*D_];
__device__ __half g_k[(size_t)M_*D_];
__device__ __half g_v[(size_t)M_*D_];

// ---------------- asm helpers ----------------
__device__ __forceinline__ uint32_t smem_u32(const void* p) {
    uint32_t a;
    asm("{ .reg .u64 t; cvta.to.shared.u64 t, %1; cvt.u32.u64 %0, t; }" : "=r"(a) : "l"(p));
    return a;
}
#define CP_ASYNC16(dst, src) \
    asm volatile("cp.async.cg.shared.global [%0], [%1], 16;" :: "r"(dst), "l"(src))
#define CP_COMMIT() asm volatile("cp.async.commit_group;" ::: "memory")
#define CP_WAIT(n)  asm volatile("cp.async.wait_group %0;" :: "n"(n) : "memory")

#define MMA_BF16(c, a, b0, b1) \
    asm volatile("mma.sync.aligned.m16n8k16.row.col.f32.bf16.bf16.f32 " \
        "{%0,%1,%2,%3}, {%4,%5,%6,%7}, {%8,%9}, {%0,%1,%2,%3};" \
        : "+f"((c)[0]), "+f"((c)[1]), "+f"((c)[2]), "+f"((c)[3]) \
        : "r"((a)[0]), "r"((a)[1]), "r"((a)[2]), "r"((a)[3]), "r"(b0), "r"(b1))

#define MMA_F16(c, a, b0, b1) \
    asm volatile("mma.sync.aligned.m16n8k16.row.col.f32.f16.f16.f32 " \
        "{%0,%1,%2,%3}, {%4,%5,%6,%7}, {%8,%9}, {%0,%1,%2,%3};" \
        : "+f"((c)[0]), "+f"((c)[1]), "+f"((c)[2]), "+f"((c)[3]) \
        : "r"((a)[0]), "r"((a)[1]), "r"((a)[2]), "r"((a)[3]), "r"(b0), "r"(b1))

#define LDSM_X4(r0,r1,r2,r3, a) \
    asm volatile("ldmatrix.sync.aligned.m8n8.x4.shared.b16 {%0,%1,%2,%3}, [%4];" \
        : "=r"(r0), "=r"(r1), "=r"(r2), "=r"(r3) : "r"(a))

#define LDSM_X4_T(r0,r1,r2,r3, a) \
    asm volatile("ldmatrix.sync.aligned.m8n8.x4.trans.shared.b16 {%0,%1,%2,%3}, [%4];" \
        : "=r"(r0), "=r"(r1), "=r"(r2), "=r"(r3) : "r"(a))

__device__ __forceinline__ uint32_t pack_bf16(float lo, float hi) {
    __nv_bfloat162 t = __floats2bfloat162_rn(lo, hi);
    return *reinterpret_cast<uint32_t*>(&t);
}
__device__ __forceinline__ uint32_t pack_f16(float lo, float hi) {
    __half2 t = __floats2half2_rn(lo, hi);
    return *reinterpret_cast<uint32_t*>(&t);
}

// ---------------- fp32 -> bf16 hi/lo split ----------------
__global__ void split_kernel(const float* __restrict__ in, const int* __restrict__ mask,
                             bf16* __restrict__ hi, bf16* __restrict__ lo,
                             int n4, int use_mask)
{
    int i = blockIdx.x * blockDim.x + threadIdx.x;
    if (i >= n4) return;
    float4 v = reinterpret_cast<const float4*>(in)[i];
    if (use_mask) {
        float mv = (float)mask[i >> 8];
        v.x *= mv; v.y *= mv; v.z *= mv; v.w *= mv;
    }
    bf16 h0 = __float2bfloat16(v.x);
    bf16 h1 = __float2bfloat16(v.y);
    bf16 h2 = __float2bfloat16(v.z);
    bf16 h3 = __float2bfloat16(v.w);
    __nv_bfloat162 hh0; hh0.x = h0; hh0.y = h1;
    __nv_bfloat162 hh1; hh1.x = h2; hh1.y = h3;
    __nv_bfloat162 ll0, ll1;
    ll0.x = __float2bfloat16(v.x - __bfloat162float(h0));
    ll0.y = __float2bfloat16(v.y - __bfloat162float(h1));
    ll1.x = __float2bfloat16(v.z - __bfloat162float(h2));
    ll1.y = __float2bfloat16(v.w - __bfloat162float(h3));
    reinterpret_cast<__nv_bfloat162*>(hi)[2*i]   = hh0;
    reinterpret_cast<__nv_bfloat162*>(hi)[2*i+1] = hh1;
    reinterpret_cast<__nv_bfloat162*>(lo)[2*i]   = ll0;
    reinterpret_cast<__nv_bfloat162*>(lo)[2*i+1] = ll1;
}

// merged weight split: grid.y selects which W
__global__ void split4_kernel(const float* __restrict__ W0, const float* __restrict__ W1,
                              const float* __restrict__ W2, const float* __restrict__ W3,
                              bf16* __restrict__ hi, bf16* __restrict__ lo, int n4)
{
    int i = blockIdx.x * blockDim.x + threadIdx.x;
    if (i >= n4) return;
    const int w = blockIdx.y;
    const float* in = (w == 0) ? W0 : (w == 1) ? W1 : (w == 2) ? W2 : W3;
    const size_t off = (size_t)w * n4;
    float4 v = reinterpret_cast<const float4*>(in)[i];
    bf16 h0 = __float2bfloat16(v.x);
    bf16 h1 = __float2bfloat16(v.y);
    bf16 h2 = __float2bfloat16(v.z);
    bf16 h3 = __float2bfloat16(v.w);
    __nv_bfloat162 hh0; hh0.x = h0; hh0.y = h1;
    __nv_bfloat162 hh1; hh1.x = h2; hh1.y = h3;
    __nv_bfloat162 ll0, ll1;
    ll0.x = __float2bfloat16(v.x - __bfloat162float(h0));
    ll0.y = __float2bfloat16(v.y - __bfloat162float(h1));
    ll1.x = __float2bfloat16(v.z - __bfloat162float(h2));
    ll1.y = __float2bfloat16(v.w - __bfloat162float(h3));
    reinterpret_cast<__nv_bfloat162*>(hi)[2*(off + i)]   = hh0;
    reinterpret_cast<__nv_bfloat162*>(hi)[2*(off + i)+1] = hh1;
    reinterpret_cast<__nv_bfloat162*>(lo)[2*(off + i)]   = ll0;
    reinterpret_cast<__nv_bfloat162*>(lo)[2*(off + i)+1] = ll1;
}

// ---------------- mma.sync split-bf16 GEMM mainloop (unchanged) ----------------
#define GS_A  40
#define G_STAGE (4*128*GS_A)    // elems per stage = 20480 (40960 B)

__device__ __forceinline__ void gemm_issue(const bf16* const srcs[4], bf16* stage,
                                           int chunk, int tid)
{
#pragma unroll
    for (int it = 0; it < 8; it++) {
        int unit = tid + it*256;
        int mat = unit >> 9, rem = unit & 511;
        int row = rem >> 2,  g  = rem & 3;
        const bf16* src = srcs[mat] + (size_t)row*D_ + chunk*32 + g*8;
        uint32_t dst = smem_u32(stage + mat*128*GS_A + row*GS_A + g*8);
        CP_ASYNC16(dst, src);
    }
}

__device__ __forceinline__ void mgemm_main(
    const bf16* __restrict__ Ah, const bf16* __restrict__ Al,
    const bf16* __restrict__ Bh, const bf16* __restrict__ Bl,
    int m0, int n0, int tid, bf16* stg0, float acc[2][8][4])
{
    bf16* stg[2] = { stg0, stg0 + G_STAGE };
    const int lane = tid & 31;
    const int wid = tid >> 5;
    const int wr = wid >> 1;
    const int wc = wid & 1;

#pragma unroll
    for (int mt = 0; mt < 2; mt++)
#pragma unroll
        for (int n = 0; n < 8; n++)
#pragma unroll
            for (int c = 0; c < 4; c++) acc[mt][n][c] = 0.0f;

    const bf16* srcs[4] = { Ah + (size_t)m0*D_, Al + (size_t)m0*D_,
                            Bh + (size_t)n0*D_, Bl + (size_t)n0*D_ };

    gemm_issue(srcs, stg[0], 0, tid); CP_COMMIT();

    const int rowA = wr*32 + ((lane >> 3) & 1)*8 + (lane & 7);
    const int colA = (lane >> 4)*8;
    const int rowB = wc*64 + (lane >> 4)*8 + (lane & 7);
    const int colB = ((lane >> 3) & 1)*8;

    for (int chunk = 0; chunk < 32; chunk++) {
        CP_WAIT(0);
        __syncthreads();
        if (chunk + 1 < 32) {
            gemm_issue(srcs, stg[(chunk + 1) & 1], chunk + 1, tid);
            CP_COMMIT();
        }

        bf16* As_h = stg[chunk & 1];
        bf16* As_l = As_h + 128*GS_A;
        bf16* Bs_h = As_l + 128*GS_A;
        bf16* Bs_l = Bs_h + 128*GS_A;

#pragma unroll
        for (int kk = 0; kk < 2; kk++) {
            uint32_t ah[2][4], al[2][4];
#pragma unroll
            for (int mt = 0; mt < 2; mt++) {
                uint32_t a = smem_u32(As_h + (rowA + mt*16)*GS_A + kk*16 + colA);
                LDSM_X4(ah[mt][0], ah[mt][1], ah[mt][2], ah[mt][3], a);
                a = smem_u32(As_l + (rowA + mt*16)*GS_A + kk*16 + colA);
                LDSM_X4(al[mt][0], al[mt][1], al[mt][2], al[mt][3], a);
            }
#pragma unroll
            for (int n4 = 0; n4 < 4; n4++) {
                uint32_t bh0, bh1, bh2, bh3, bl0, bl1, bl2, bl3;
                uint32_t a = smem_u32(Bs_h + (rowB + n4*16)*GS_A + kk*16 + colB);
                LDSM_X4(bh0, bh1, bh2, bh3, a);
                a = smem_u32(Bs_l + (rowB + n4*16)*GS_A + kk*16 + colB);
                LDSM_X4(bl0, bl1, bl2, bl3, a);
#pragma unroll
                for (int mt = 0; mt < 2; mt++) {
                    MMA_BF16(acc[mt][2*n4],   ah[mt], bh0, bh1);
                    MMA_BF16(acc[mt][2*n4],   ah[mt], bl0, bl1);
                    MMA_BF16(acc[mt][2*n4],   al[mt], bh0, bh1);
                    MMA_BF16(acc[mt][2*n4+1], ah[mt], bh2, bh3);
                    MMA_BF16(acc[mt][2*n4+1], ah[mt], bl2, bl3);
                    MMA_BF16(acc[mt][2*n4+1], al[mt], bh2, bh3);
                }
            }
        }
    }
}

// merged QKV GEMM: grid.x = 24 (proj = bx>>3, ntile = bx&7); fp16-single epilogue
__global__ void __launch_bounds__(256, 2) mgemm_qkv_kernel(
    const bf16* __restrict__ Ah, const bf16* __restrict__ Al,
    const bf16* __restrict__ Wh, const bf16* __restrict__ Wl,
    const float* __restrict__ bq, const float* __restrict__ bk, const float* __restrict__ bv,
    __half* __restrict__ qf, __half* __restrict__ kf, __half* __restrict__ vf)
{
    extern __shared__ char smraw[];
    __shared__ float sbias[128];
    const int tid = threadIdx.x;
    const int lane = tid & 31;
    const int wid = tid >> 5;
    const int wr = wid >> 1;
    const int wc = wid & 1;
    const int proj = blockIdx.x >> 3;
    const int n0 = (blockIdx.x & 7) * 128;
    const int m0 = blockIdx.y * 128;
    const size_t WSZ = (size_t)D_ * D_;

    const float* bias = (proj == 0) ? bq : (proj == 1) ? bk : bv;
    __half* C = (proj == 0) ? qf : (proj == 1) ? kf : vf;
    if (tid < 128) sbias[tid] = bias[n0 + tid];

    float acc[2][8][4];
    mgemm_main(Ah, Al, Wh + proj*WSZ, Wl + proj*WSZ, m0, n0, tid, (bf16*)smraw, acc);

    const int cb = (lane & 3)*2;
    const int e_loc = wc*64 + cb;
    const int h = (n0 + wc*64) >> 6;
#pragma unroll
    for (int mt = 0; mt < 2; mt++) {
#pragma unroll
        for (int half = 0; half < 2; half++) {
            const int m = m0 + wr*32 + mt*16 + half*8 + (lane >> 2);
            const int b = m >> 11, s = m & 2047;
            const size_t base = (((size_t)(b*H_ + h))*S_ + s)*HD_;
#pragma unroll
            for (int n = 0; n < 8; n++) {
                float v0 = acc[mt][n][half*2]     + sbias[e_loc + n*8];
                float v1 = acc[mt][n][half*2 + 1] + sbias[e_loc + n*8 + 1];
                *reinterpret_cast<uint32_t*>(C + base + n*8 + cb) = pack_f16(v0, v1);
            }
        }
    }
}

// O-projection GEMM (fp32 out * rowmask), register epilogue (unchanged)
__global__ void __launch_bounds__(256, 2) mgemm_o_kernel(
    const bf16* __restrict__ Ah, const bf16* __restrict__ Al,
    const bf16* __restrict__ Bh, const bf16* __restrict__ Bl,
    const float* __restrict__ bias, const int* __restrict__ mask,
    float* __restrict__ Cf)
{
    extern __shared__ char smraw[];
    __shared__ float sbias[128];
    const int tid = threadIdx.x;
    const int lane = tid & 31;
    const int wid = tid >> 5;
    const int wr = wid >> 1;
    const int wc = wid & 1;
    const int m0 = blockIdx.y * 128;
    const int n0 = blockIdx.x * 128;
    if (tid < 128) sbias[tid] = bias[n0 + tid];

    float acc[2][8][4];
    mgemm_main(Ah, Al, Bh, Bl, m0, n0, tid, (bf16*)smraw, acc);

    const int cb = (lane & 3)*2;
    const int e_loc = wc*64 + cb;
#pragma unroll
    for (int mt = 0; mt < 2; mt++) {
#pragma unroll
        for (int half = 0; half < 2; half++) {
            const int m = m0 + wr*32 + mt*16 + half*8 + (lane >> 2);
            const float maskv = (float)mask[m];
            float* outp = Cf + (size_t)m*D_ + n0;
#pragma unroll
            for (int n = 0; n < 8; n++) {
                float2 v;
                v.x = (acc[mt][n][half*2]     + sbias[e_loc + n*8])     * maskv;
                v.y = (acc[mt][n][half*2 + 1] + sbias[e_loc + n*8 + 1]) * maskv;
                *reinterpret_cast<float2*>(outp + e_loc + n*8) = v;
            }
        }
    }
}

// ---------------- fp16 1-pass attention: 3-stage (Q aliased with stage2) ----------------
#define AS_B 72
#define A_KTILE (64*AS_B)                 // elems per 64x64 fp16 tile
#define A_TILES_B (2*A_KTILE*2)           // K+V bytes = 18432
#define A_STAGE_B (A_TILES_B + 256)       // + 64 int mask slot = 18688
#define A_QTILE (128*AS_B)                // Q elems (fp16, 18432 B <= stage)

__device__ __forceinline__ void attn_issue(const __half* kf, const __half* vf,
                                           const int* __restrict__ maskp,
                                           char* stage, int kb, int tid)
{
    __half* st = (__half*)stage;
#pragma unroll
    for (int it = 0; it < 2; it++) {
        int unit = tid + it*256;            // 0..511
        int row = unit >> 3, g = unit & 7;
        const size_t go = (size_t)(kb + row)*HD_ + g*8;
        const int so = row*AS_B + g*8;
        CP_ASYNC16(smem_u32(st + so), kf + go);
        CP_ASYNC16(smem_u32(st + A_KTILE + so), vf + go);
    }
    if (tid < 16)
        CP_ASYNC16(smem_u32(stage + A_TILES_B + tid*16), maskp + kb + tid*4);
}

__global__ void __launch_bounds__(256, 2) mattn_kernel(const int* __restrict__ mask)
{
    extern __shared__ char smraw[];
    char* stg[3] = { smraw, smraw + A_STAGE_B, smraw + 2*A_STAGE_B };
    __half* Qs = (__half*)stg[2];   // Q aliases stage 2 (consumed before stage 2 first written)

    const int tid  = threadIdx.x;
    const int lane = tid & 31;
    const int ti   = tid >> 5;
    const int bh = blockIdx.y;
    const int b  = bh >> 4, h = bh & 15;
    const int q0 = blockIdx.x << 7;

    const __half* Kg = g_k + (size_t)bh*S_*HD_;
    const __half* Vg = g_v + (size_t)bh*S_*HD_;
    const int* maskp = mask + b*S_;

    attn_issue(Kg, Vg, maskp, stg[0], 0,  tid); CP_COMMIT();
    attn_issue(Kg, Vg, maskp, stg[1], 64, tid); CP_COMMIT();

    // load Q (fp16 single) into stage-2 area while cp.async flies
    const __half* Qg = g_q + ((size_t)bh*S_ + q0)*HD_;
#pragma unroll
    for (int it = 0; it < 2; it++) {
        int unit = tid + it*256;            // 0..511 covers 64 rows; need 128 rows -> 4 iters of 256?
        int row = unit >> 3, c8 = unit & 7;
        *reinterpret_cast<uint4*>(Qs + row*AS_B + c8*8) =
            *reinterpret_cast<const uint4*>(Qg + (size_t)row*HD_ + c8*8);
        int row2 = row + 64;
        *reinterpret_cast<uint4*>(Qs + row2*AS_B + c8*8) =
            *reinterpret_cast<const uint4*>(Qg + (size_t)row2*HD_ + c8*8);
    }
    __syncthreads();   // Q visible

    uint32_t qf[4][4];
    {
        const int rowQ = ti*16 + ((lane >> 3) & 1)*8 + (lane & 7);
        const int colQ = (lane >> 4)*8;
#pragma unroll
        for (int g = 0; g < 4; g++) {
            uint32_t a = smem_u32(Qs + rowQ*AS_B + g*16 + colQ);
            LDSM_X4(qf[g][0], qf[g][1], qf[g][2], qf[g][3], a);
        }
    }
    __syncthreads();   // all warps done reading Q -> stage 2 free for kt=2

    float oc[8][4];
#pragma unroll
    for (int n = 0; n < 8; n++)
#pragma unroll
        for (int c = 0; c < 4; c++) oc[n][c] = 0.0f;
    float lp0 = 0.0f, lp1 = 0.0f;

    const int rowK = (lane >> 4)*8 + (lane & 7);
    const int colK = ((lane >> 3) & 1)*8;
    const int rowV = ((lane >> 3) & 1)*8 + (lane & 7);
    const int colV = (lane >> 4)*8;
    const int cb   = (lane & 3)*2;

    for (int kt = 0; kt < 32; kt++) {
        if (kt < 31) { CP_WAIT(1); } else { CP_WAIT(0); }
        __syncthreads();   // stage kt visible; stage (kt+2)%3 drained
        if (kt + 2 < 32) {
            attn_issue(Kg, Vg, maskp, stg[(kt + 2) % 3], (kt + 2) << 6, tid);
            CP_COMMIT();
        }

        char* st = stg[kt % 3];
        __half* Kf = (__half*)st;
        __half* Vf = Kf + A_KTILE;
        const int* kmi = (const int*)(st + A_TILES_B);

        // ---- S = Q K^T (1 pass, fp16) ----
        float sc[8][4];
#pragma unroll
        for (int n = 0; n < 8; n++)
#pragma unroll
            for (int c = 0; c < 4; c++) sc[n][c] = 0.0f;

#pragma unroll
        for (int g = 0; g < 4; g++) {
#pragma unroll
            for (int n2 = 0; n2 < 4; n2++) {
                uint32_t k0, k1, k2, k3;
                uint32_t a = smem_u32(Kf + (n2*16 + rowK)*AS_B + g*16 + colK);
                LDSM_X4(k0, k1, k2, k3, a);
                MMA_F16(sc[2*n2],   qf[g], k0, k1);
                MMA_F16(sc[2*n2+1], qf[g], k2, k3);
            }
        }

        // ---- batched exp: all 32 elements ----
#pragma unroll
        for (int n = 0; n < 8; n++) {
            const int colb = n*8 + cb;
            const float km0 = (float)kmi[colb];
            const float km1 = (float)kmi[colb + 1];
            float p0 = __expf(sc[n][0] * 0.125f) * km0;
            float p1 = __expf(sc[n][1] * 0.125f) * km1;
            float p2 = __expf(sc[n][2] * 0.125f) * km0;
            float p3 = __expf(sc[n][3] * 0.125f) * km1;
            lp0 += p0 + p1;
            lp1 += p2 + p3;
            sc[n][0] = p0; sc[n][1] = p1; sc[n][2] = p2; sc[n][3] = p3;
        }

        // ---- pack P to fp16 + PV (1 pass) per 16-key group ----
#pragma unroll
        for (int g = 0; g < 4; g++) {
            uint32_t pf[4];
#pragma unroll
            for (int nn = 0; nn < 2; nn++) {
                const int n = 2*g + nn;
                pf[nn*2]     = pack_f16(sc[n][0], sc[n][1]);
                pf[nn*2 + 1] = pack_f16(sc[n][2], sc[n][3]);
            }
#pragma unroll
            for (int d2 = 0; d2 < 4; d2++) {
                uint32_t v0, v1, v2, v3;
                uint32_t a = smem_u32(Vf + (g*16 + rowV)*AS_B + d2*16 + colV);
                LDSM_X4_T(v0, v1, v2, v3, a);
                MMA_F16(oc[2*d2],   pf, v0, v1);
                MMA_F16(oc[2*d2+1], pf, v2, v3);
            }
        }
    }

    lp0 += __shfl_xor_sync(0xffffffffu, lp0, 1);
    lp0 += __shfl_xor_sync(0xffffffffu, lp0, 2);
    lp1 += __shfl_xor_sync(0xffffffffu, lp1, 1);
    lp1 += __shfl_xor_sync(0xffffffffu, lp1, 2);
    const float inv0 = (lp0 > 0.f) ? (1.0f / lp0) : 0.f;
    const float inv1 = (lp1 > 0.f) ? (1.0f / lp1) : 0.f;

    // ctx written as bf16 hi/lo (keeps O-projection at full precision)
    const int row0 = q0 + ti*16 + (lane >> 2);
    const size_t base0 = ((size_t)(b*S_ + row0))*D_ + h*HD_ + cb;
    const size_t base1 = base0 + 8*(size_t)D_;
#pragma unroll
    for (int n = 0; n < 8; n++) {
        float v00 = oc[n][0]*inv0, v01 = oc[n][1]*inv0;
        float v10 = oc[n][2]*inv1, v11 = oc[n][3]*inv1;
        float h00 = __bfloat162float(__float2bfloat16(v00));
        float h01 = __bfloat162float(__float2bfloat16(v01));
        float h10 = __bfloat162float(__float2bfloat16(v10));
        float h11 = __bfloat162float(__float2bfloat16(v11));
        *reinterpret_cast<uint32_t*>(g_xh + base0 + n*8) = pack_bf16(h00, h01);
        *reinterpret_cast<uint32_t*>(g_xh + base1 + n*8) = pack_bf16(h10, h11);
        *reinterpret_cast<uint32_t*>(g_xl + base0 + n*8) = pack_bf16(v00 - h00, v01 - h01);
        *reinterpret_cast<uint32_t*>(g_xl + base1 + n*8) = pack_bf16(v10 - h10, v11 - h11);
    }
}

// ---------------- launch ----------------
extern "C" void kernel_launch(void* const* d_in, const int* in_sizes, int n_in,
                              void* d_out, int out_size)
{
    const float* hidden = (const float*)d_in[0];
    const int*   mask   = (const int*)d_in[1];
    const float* Wq = (const float*)d_in[2];
    const float* bq = (const float*)d_in[3];
    const float* Wk = (const float*)d_in[4];
    const float* bk = (const float*)d_in[5];
    const float* Wv = (const float*)d_in[6];
    const float* bv = (const float*)d_in[7];
    const float* Wo = (const float*)d_in[8];
    const float* bo = (const float*)d_in[9];
    float* out = (float*)d_out;

    bf16 *xh, *xl, *wh, *wl;
    __half *qf, *kf, *vf;
    cudaGetSymbolAddress((void**)&xh, g_xh);
    cudaGetSymbolAddress((void**)&xl, g_xl);
    cudaGetSymbolAddress((void**)&wh, g_wh);
    cudaGetSymbolAddress((void**)&wl, g_wl);
    cudaGetSymbolAddress((void**)&qf, g_q);
    cudaGetSymbolAddress((void**)&kf, g_k);
    cudaGetSymbolAddress((void**)&vf, g_v);

    const size_t WSZ = (size_t)D_ * D_;
    const int xn4 = (M_ * D_) / 4;
    const int wn4 = (D_ * D_) / 4;

    split_kernel<<<(xn4 + 255)/256, 256>>>(hidden, mask, xh, xl, xn4, 1);
    split4_kernel<<<dim3((wn4 + 255)/256, 4), 256>>>(Wq, Wk, Wv, Wo, wh, wl, wn4);

    const int gsmem = 2 * G_STAGE * (int)sizeof(bf16);   // 81920
    cudaFuncSetAttribute(mgemm_qkv_kernel, cudaFuncAttributeMaxDynamicSharedMemorySize, gsmem);
    cudaFuncSetAttribute(mgemm_o_kernel,   cudaFuncAttributeMaxDynamicSharedMemorySize, gsmem);

    mgemm_qkv_kernel<<<dim3(24, M_/128), 256, gsmem>>>(
        xh, xl, wh, wl, bq, bk, bv, qf, kf, vf);

    const int asmem = 3 * A_STAGE_B;   // 56064
    cudaFuncSetAttribute(mattn_kernel, cudaFuncAttributeMaxDynamicSharedMemorySize, asmem);
    mattn_kernel<<<dim3(S_/128, B_*H_), 256, asmem>>>(mask);

    mgemm_o_kernel<<<dim3(D_/128, M_/128), 256, gsmem>>>(
        xh, xl, wh + 3*WSZ, wl + 3*WSZ, bo, mask, out);
}

// round 13
// speedup vs baseline: 1.8617x; 1.3341x over previous
#include <cuda_runtime.h>
#include <cuda_bf16.h>
#include <cuda_fp16.h>
#include <math.h>
#include <stdint.h>

#define B_  4
#define S_  2048
#define D_  1024
#define H_  16
#define HD_ 64
#define M_  (B_*S_)

// ---------------- scratch ----------------
__device__ __half g_xh[(size_t)M_*D_];   // activations hi (hidden, then ctx)
__device__ __half g_xl[(size_t)M_*D_];   // activations lo
__device__ __half g_w[(size_t)4*D_*D_];  // weights, single fp16
__device__ __half g_q[(size_t)M_*D_];
__device__ __half g_k[(size_t)M_*D_];
__device__ __half g_v[(size_t)M_*D_];

// ---------------- asm helpers ----------------
__device__ __forceinline__ uint32_t smem_u32(const void* p) {
    uint32_t a;
    asm("{ .reg .u64 t; cvta.to.shared.u64 t, %1; cvt.u32.u64 %0, t; }" : "=r"(a) : "l"(p));
    return a;
}
#define CP_ASYNC16(dst, src) \
    asm volatile("cp.async.cg.shared.global [%0], [%1], 16;" :: "r"(dst), "l"(src))
#define CP_COMMIT() asm volatile("cp.async.commit_group;" ::: "memory")
#define CP_WAIT(n)  asm volatile("cp.async.wait_group %0;" :: "n"(n) : "memory")

#define MMA_F16(c, a, b0, b1) \
    asm volatile("mma.sync.aligned.m16n8k16.row.col.f32.f16.f16.f32 " \
        "{%0,%1,%2,%3}, {%4,%5,%6,%7}, {%8,%9}, {%0,%1,%2,%3};" \
        : "+f"((c)[0]), "+f"((c)[1]), "+f"((c)[2]), "+f"((c)[3]) \
        : "r"((a)[0]), "r"((a)[1]), "r"((a)[2]), "r"((a)[3]), "r"(b0), "r"(b1))

#define LDSM_X4(r0,r1,r2,r3, a) \
    asm volatile("ldmatrix.sync.aligned.m8n8.x4.shared.b16 {%0,%1,%2,%3}, [%4];" \
        : "=r"(r0), "=r"(r1), "=r"(r2), "=r"(r3) : "r"(a))

#define LDSM_X4_T(r0,r1,r2,r3, a) \
    asm volatile("ldmatrix.sync.aligned.m8n8.x4.trans.shared.b16 {%0,%1,%2,%3}, [%4];" \
        : "=r"(r0), "=r"(r1), "=r"(r2), "=r"(r3) : "r"(a))

__device__ __forceinline__ uint32_t pack_f16(float lo, float hi) {
    __half2 t = __floats2half2_rn(lo, hi);
    return *reinterpret_cast<uint32_t*>(&t);
}

// ---------------- fp32 -> fp16 hi/lo split (activations) ----------------
__global__ void split_kernel(const float* __restrict__ in, const int* __restrict__ mask,
                             __half* __restrict__ hi, __half* __restrict__ lo,
                             int n4, int use_mask)
{
    int i = blockIdx.x * blockDim.x + threadIdx.x;
    if (i >= n4) return;
    float4 v = reinterpret_cast<const float4*>(in)[i];
    if (use_mask) {
        float mv = (float)mask[i >> 8];
        v.x *= mv; v.y *= mv; v.z *= mv; v.w *= mv;
    }
    __half h0 = __float2half(v.x);
    __half h1 = __float2half(v.y);
    __half h2 = __float2half(v.z);
    __half h3 = __float2half(v.w);
    reinterpret_cast<uint32_t*>(hi)[2*i]   = pack_f16(__half2float(h0)*0.f + v.x, v.y); // placeholder avoided below
    // (overwritten correctly below)
    __half2 hh0; hh0.x = h0; hh0.y = h1;
    __half2 hh1; hh1.x = h2; hh1.y = h3;
    __half2 ll0, ll1;
    ll0.x = __float2half(v.x - __half2float(h0));
    ll0.y = __float2half(v.y - __half2float(h1));
    ll1.x = __float2half(v.z - __half2float(h2));
    ll1.y = __float2half(v.w - __half2float(h3));
    reinterpret_cast<__half2*>(hi)[2*i]   = hh0;
    reinterpret_cast<__half2*>(hi)[2*i+1] = hh1;
    reinterpret_cast<__half2*>(lo)[2*i]   = ll0;
    reinterpret_cast<__half2*>(lo)[2*i+1] = ll1;
}

// merged weight convert: single fp16, grid.y selects which W
__global__ void split4_kernel(const float* __restrict__ W0, const float* __restrict__ W1,
                              const float* __restrict__ W2, const float* __restrict__ W3,
                              __half* __restrict__ wout, int n4)
{
    int i = blockIdx.x * blockDim.x + threadIdx.x;
    if (i >= n4) return;
    const int w = blockIdx.y;
    const float* in = (w == 0) ? W0 : (w == 1) ? W1 : (w == 2) ? W2 : W3;
    const size_t off = (size_t)w * n4;
    float4 v = reinterpret_cast<const float4*>(in)[i];
    __half2 a; a.x = __float2half(v.x); a.y = __float2half(v.y);
    __half2 b; b.x = __float2half(v.z); b.y = __float2half(v.w);
    reinterpret_cast<__half2*>(wout)[2*(off + i)]     = a;
    reinterpret_cast<__half2*>(wout)[2*(off + i) + 1] = b;
}

// ---------------- 2-pass fp16 GEMM: C = (Ah+Al) @ W^T + bias ----------------
// k-chunk 64, smem row stride 72 fp16 (144 B), 2-stage ring, 2 CTAs/SM.
#define GS_A  72
#define G_STAGE (3*128*GS_A)    // fp16 elems per stage (Ah, Al, W tiles)

__device__ __forceinline__ void gemm_issue(const __half* const srcs[3], __half* stage,
                                           int chunk, int tid)
{
#pragma unroll
    for (int it = 0; it < 12; it++) {
        int unit = tid + it*256;            // 0..3071
        int mat = unit >> 10, rem = unit & 1023;
        int row = rem >> 3,  g  = rem & 7;
        const __half* src = srcs[mat] + (size_t)row*D_ + chunk*64 + g*8;
        uint32_t dst = smem_u32(stage + mat*128*GS_A + row*GS_A + g*8);
        CP_ASYNC16(dst, src);
    }
}

__device__ __forceinline__ void mgemm_main(
    const __half* __restrict__ Ah, const __half* __restrict__ Al,
    const __half* __restrict__ W,
    int m0, int n0, int tid, __half* stg0, float acc[2][8][4])
{
    __half* stg[2] = { stg0, stg0 + G_STAGE };
    const int lane = tid & 31;
    const int wid = tid >> 5;
    const int wr = wid >> 1;
    const int wc = wid & 1;

#pragma unroll
    for (int mt = 0; mt < 2; mt++)
#pragma unroll
        for (int n = 0; n < 8; n++)
#pragma unroll
            for (int c = 0; c < 4; c++) acc[mt][n][c] = 0.0f;

    const __half* srcs[3] = { Ah + (size_t)m0*D_, Al + (size_t)m0*D_,
                              W  + (size_t)n0*D_ };

    gemm_issue(srcs, stg[0], 0, tid); CP_COMMIT();

    const int rowA = wr*32 + ((lane >> 3) & 1)*8 + (lane & 7);
    const int colA = (lane >> 4)*8;
    const int rowB = wc*64 + (lane >> 4)*8 + (lane & 7);
    const int colB = ((lane >> 3) & 1)*8;

    for (int chunk = 0; chunk < 16; chunk++) {
        CP_WAIT(0);
        __syncthreads();
        if (chunk + 1 < 16) {
            gemm_issue(srcs, stg[(chunk + 1) & 1], chunk + 1, tid);
            CP_COMMIT();
        }

        __half* As_h = stg[chunk & 1];
        __half* As_l = As_h + 128*GS_A;
        __half* Ws   = As_l + 128*GS_A;

#pragma unroll
        for (int kk = 0; kk < 4; kk++) {
            uint32_t ah[2][4], al[2][4];
#pragma unroll
            for (int mt = 0; mt < 2; mt++) {
                uint32_t a = smem_u32(As_h + (rowA + mt*16)*GS_A + kk*16 + colA);
                LDSM_X4(ah[mt][0], ah[mt][1], ah[mt][2], ah[mt][3], a);
                a = smem_u32(As_l + (rowA + mt*16)*GS_A + kk*16 + colA);
                LDSM_X4(al[mt][0], al[mt][1], al[mt][2], al[mt][3], a);
            }
#pragma unroll
            for (int n4 = 0; n4 < 4; n4++) {
                uint32_t w0, w1, w2, w3;
                uint32_t a = smem_u32(Ws + (rowB + n4*16)*GS_A + kk*16 + colB);
                LDSM_X4(w0, w1, w2, w3, a);
#pragma unroll
                for (int mt = 0; mt < 2; mt++) {
                    MMA_F16(acc[mt][2*n4],   ah[mt], w0, w1);
                    MMA_F16(acc[mt][2*n4],   al[mt], w0, w1);
                    MMA_F16(acc[mt][2*n4+1], ah[mt], w2, w3);
                    MMA_F16(acc[mt][2*n4+1], al[mt], w2, w3);
                }
            }
        }
    }
}

// merged QKV GEMM: grid.x = 24 (proj = bx>>3, ntile = bx&7); fp16-single epilogue
__global__ void __launch_bounds__(256, 2) mgemm_qkv_kernel(
    const __half* __restrict__ Ah, const __half* __restrict__ Al,
    const __half* __restrict__ W,
    const float* __restrict__ bq, const float* __restrict__ bk, const float* __restrict__ bv,
    __half* __restrict__ qf, __half* __restrict__ kf, __half* __restrict__ vf)
{
    extern __shared__ char smraw[];
    __shared__ float sbias[128];
    const int tid = threadIdx.x;
    const int lane = tid & 31;
    const int wid = tid >> 5;
    const int wr = wid >> 1;
    const int wc = wid & 1;
    const int proj = blockIdx.x >> 3;
    const int n0 = (blockIdx.x & 7) * 128;
    const int m0 = blockIdx.y * 128;
    const size_t WSZ = (size_t)D_ * D_;

    const float* bias = (proj == 0) ? bq : (proj == 1) ? bk : bv;
    __half* C = (proj == 0) ? qf : (proj == 1) ? kf : vf;
    if (tid < 128) sbias[tid] = bias[n0 + tid];

    float acc[2][8][4];
    mgemm_main(Ah, Al, W + proj*WSZ, m0, n0, tid, (__half*)smraw, acc);

    const int cb = (lane & 3)*2;
    const int e_loc = wc*64 + cb;
    const int h = (n0 + wc*64) >> 6;
#pragma unroll
    for (int mt = 0; mt < 2; mt++) {
#pragma unroll
        for (int half = 0; half < 2; half++) {
            const int m = m0 + wr*32 + mt*16 + half*8 + (lane >> 2);
            const int b = m >> 11, s = m & 2047;
            const size_t base = (((size_t)(b*H_ + h))*S_ + s)*HD_;
#pragma unroll
            for (int n = 0; n < 8; n++) {
                float v0 = acc[mt][n][half*2]     + sbias[e_loc + n*8];
                float v1 = acc[mt][n][half*2 + 1] + sbias[e_loc + n*8 + 1];
                *reinterpret_cast<uint32_t*>(C + base + n*8 + cb) = pack_f16(v0, v1);
            }
        }
    }
}

// O-projection GEMM (fp32 out * rowmask)
__global__ void __launch_bounds__(256, 2) mgemm_o_kernel(
    const __half* __restrict__ Ah, const __half* __restrict__ Al,
    const __half* __restrict__ W,
    const float* __restrict__ bias, const int* __restrict__ mask,
    float* __restrict__ Cf)
{
    extern __shared__ char smraw[];
    __shared__ float sbias[128];
    const int tid = threadIdx.x;
    const int lane = tid & 31;
    const int wid = tid >> 5;
    const int wr = wid >> 1;
    const int wc = wid & 1;
    const int m0 = blockIdx.y * 128;
    const int n0 = blockIdx.x * 128;
    if (tid < 128) sbias[tid] = bias[n0 + tid];

    float acc[2][8][4];
    mgemm_main(Ah, Al, W, m0, n0, tid, (__half*)smraw, acc);

    const int cb = (lane & 3)*2;
    const int e_loc = wc*64 + cb;
#pragma unroll
    for (int mt = 0; mt < 2; mt++) {
#pragma unroll
        for (int half = 0; half < 2; half++) {
            const int m = m0 + wr*32 + mt*16 + half*8 + (lane >> 2);
            const float maskv = (float)mask[m];
            float* outp = Cf + (size_t)m*D_ + n0;
#pragma unroll
            for (int n = 0; n < 8; n++) {
                float2 v;
                v.x = (acc[mt][n][half*2]     + sbias[e_loc + n*8])     * maskv;
                v.y = (acc[mt][n][half*2 + 1] + sbias[e_loc + n*8 + 1]) * maskv;
                *reinterpret_cast<float2*>(outp + e_loc + n*8) = v;
            }
        }
    }
}

// ---------------- fp16 1-pass attention (unchanged from R12 except ctx fp16 out) ----------------
#define AS_B 72
#define A_KTILE (64*AS_B)
#define A_TILES_B (2*A_KTILE*2)           // K+V bytes = 18432
#define A_STAGE_B (A_TILES_B + 256)       // + mask slot = 18688
#define A_QTILE (128*AS_B)

__device__ __forceinline__ void attn_issue(const __half* kf, const __half* vf,
                                           const int* __restrict__ maskp,
                                           char* stage, int kb, int tid)
{
    __half* st = (__half*)stage;
#pragma unroll
    for (int it = 0; it < 2; it++) {
        int unit = tid + it*256;
        int row = unit >> 3, g = unit & 7;
        const size_t go = (size_t)(kb + row)*HD_ + g*8;
        const int so = row*AS_B + g*8;
        CP_ASYNC16(smem_u32(st + so), kf + go);
        CP_ASYNC16(smem_u32(st + A_KTILE + so), vf + go);
    }
    if (tid < 16)
        CP_ASYNC16(smem_u32(stage + A_TILES_B + tid*16), maskp + kb + tid*4);
}

__global__ void __launch_bounds__(256, 2) mattn_kernel(const int* __restrict__ mask)
{
    extern __shared__ char smraw[];
    char* stg[3] = { smraw, smraw + A_STAGE_B, smraw + 2*A_STAGE_B };
    __half* Qs = (__half*)stg[2];   // Q aliases stage 2

    const int tid  = threadIdx.x;
    const int lane = tid & 31;
    const int ti   = tid >> 5;
    const int bh = blockIdx.y;
    const int b  = bh >> 4, h = bh & 15;
    const int q0 = blockIdx.x << 7;

    const __half* Kg = g_k + (size_t)bh*S_*HD_;
    const __half* Vg = g_v + (size_t)bh*S_*HD_;
    const int* maskp = mask + b*S_;

    attn_issue(Kg, Vg, maskp, stg[0], 0,  tid); CP_COMMIT();
    attn_issue(Kg, Vg, maskp, stg[1], 64, tid); CP_COMMIT();

    const __half* Qg = g_q + ((size_t)bh*S_ + q0)*HD_;
#pragma unroll
    for (int it = 0; it < 2; it++) {
        int unit = tid + it*256;
        int row = unit >> 3, c8 = unit & 7;
        *reinterpret_cast<uint4*>(Qs + row*AS_B + c8*8) =
            *reinterpret_cast<const uint4*>(Qg + (size_t)row*HD_ + c8*8);
        int row2 = row + 64;
        *reinterpret_cast<uint4*>(Qs + row2*AS_B + c8*8) =
            *reinterpret_cast<const uint4*>(Qg + (size_t)row2*HD_ + c8*8);
    }
    __syncthreads();

    uint32_t qf[4][4];
    {
        const int rowQ = ti*16 + ((lane >> 3) & 1)*8 + (lane & 7);
        const int colQ = (lane >> 4)*8;
#pragma unroll
        for (int g = 0; g < 4; g++) {
            uint32_t a = smem_u32(Qs + rowQ*AS_B + g*16 + colQ);
            LDSM_X4(qf[g][0], qf[g][1], qf[g][2], qf[g][3], a);
        }
    }
    __syncthreads();

    float oc[8][4];
#pragma unroll
    for (int n = 0; n < 8; n++)
#pragma unroll
        for (int c = 0; c < 4; c++) oc[n][c] = 0.0f;
    float lp0 = 0.0f, lp1 = 0.0f;

    const int rowK = (lane >> 4)*8 + (lane & 7);
    const int colK = ((lane >> 3) & 1)*8;
    const int rowV = ((lane >> 3) & 1)*8 + (lane & 7);
    const int colV = (lane >> 4)*8;
    const int cb   = (lane & 3)*2;

    for (int kt = 0; kt < 32; kt++) {
        if (kt < 31) { CP_WAIT(1); } else { CP_WAIT(0); }
        __syncthreads();
        if (kt + 2 < 32) {
            attn_issue(Kg, Vg, maskp, stg[(kt + 2) % 3], (kt + 2) << 6, tid);
            CP_COMMIT();
        }

        char* st = stg[kt % 3];
        __half* Kf = (__half*)st;
        __half* Vf = Kf + A_KTILE;
        const int* kmi = (const int*)(st + A_TILES_B);

        float sc[8][4];
#pragma unroll
        for (int n = 0; n < 8; n++)
#pragma unroll
            for (int c = 0; c < 4; c++) sc[n][c] = 0.0f;

#pragma unroll
        for (int g = 0; g < 4; g++) {
#pragma unroll
            for (int n2 = 0; n2 < 4; n2++) {
                uint32_t k0, k1, k2, k3;
                uint32_t a = smem_u32(Kf + (n2*16 + rowK)*AS_B + g*16 + colK);
                LDSM_X4(k0, k1, k2, k3, a);
                MMA_F16(sc[2*n2],   qf[g], k0, k1);
                MMA_F16(sc[2*n2+1], qf[g], k2, k3);
            }
        }

#pragma unroll
        for (int n = 0; n < 8; n++) {
            const int colb = n*8 + cb;
            const float km0 = (float)kmi[colb];
            const float km1 = (float)kmi[colb + 1];
            float p0 = __expf(sc[n][0] * 0.125f) * km0;
            float p1 = __expf(sc[n][1] * 0.125f) * km1;
            float p2 = __expf(sc[n][2] * 0.125f) * km0;
            float p3 = __expf(sc[n][3] * 0.125f) * km1;
            lp0 += p0 + p1;
            lp1 += p2 + p3;
            sc[n][0] = p0; sc[n][1] = p1; sc[n][2] = p2; sc[n][3] = p3;
        }

#pragma unroll
        for (int g = 0; g < 4; g++) {
            uint32_t pf[4];
#pragma unroll
            for (int nn = 0; nn < 2; nn++) {
                const int n = 2*g + nn;
                pf[nn*2]     = pack_f16(sc[n][0], sc[n][1]);
                pf[nn*2 + 1] = pack_f16(sc[n][2], sc[n][3]);
            }
#pragma unroll
            for (int d2 = 0; d2 < 4; d2++) {
                uint32_t v0, v1, v2, v3;
                uint32_t a = smem_u32(Vf + (g*16 + rowV)*AS_B + d2*16 + colV);
                LDSM_X4_T(v0, v1, v2, v3, a);
                MMA_F16(oc[2*d2],   pf, v0, v1);
                MMA_F16(oc[2*d2+1], pf, v2, v3);
            }
        }
    }

    lp0 += __shfl_xor_sync(0xffffffffu, lp0, 1);
    lp0 += __shfl_xor_sync(0xffffffffu, lp0, 2);
    lp1 += __shfl_xor_sync(0xffffffffu, lp1, 1);
    lp1 += __shfl_xor_sync(0xffffffffu, lp1, 2);
    const float inv0 = (lp0 > 0.f) ? (1.0f / lp0) : 0.f;
    const float inv1 = (lp1 > 0.f) ? (1.0f / lp1) : 0.f;

    // ctx written as fp16 hi/lo (O-projection consumes 2-pass)
    const int row0 = q0 + ti*16 + (lane >> 2);
    const size_t base0 = ((size_t)(b*S_ + row0))*D_ + h*HD_ + cb;
    const size_t base1 = base0 + 8*(size_t)D_;
#pragma unroll
    for (int n = 0; n < 8; n++) {
        float v00 = oc[n][0]*inv0, v01 = oc[n][1]*inv0;
        float v10 = oc[n][2]*inv1, v11 = oc[n][3]*inv1;
        __half h00 = __float2half(v00), h01 = __float2half(v01);
        __half h10 = __float2half(v10), h11 = __float2half(v11);
        __half2 a0; a0.x = h00; a0.y = h01;
        __half2 a1; a1.x = h10; a1.y = h11;
        *reinterpret_cast<__half2*>(g_xh + base0 + n*8) = a0;
        *reinterpret_cast<__half2*>(g_xh + base1 + n*8) = a1;
        *reinterpret_cast<uint32_t*>(g_xl + base0 + n*8) =
            pack_f16(v00 - __half2float(h00), v01 - __half2float(h01));
        *reinterpret_cast<uint32_t*>(g_xl + base1 + n*8) =
            pack_f16(v10 - __half2float(h10), v11 - __half2float(h11));
    }
}

// ---------------- launch ----------------
extern "C" void kernel_launch(void* const* d_in, const int* in_sizes, int n_in,
                              void* d_out, int out_size)
{
    const float* hidden = (const float*)d_in[0];
    const int*   mask   = (const int*)d_in[1];
    const float* Wq = (const float*)d_in[2];
    const float* bq = (const float*)d_in[3];
    const float* Wk = (const float*)d_in[4];
    const float* bk = (const float*)d_in[5];
    const float* Wv = (const float*)d_in[6];
    const float* bv = (const float*)d_in[7];
    const float* Wo = (const float*)d_in[8];
    const float* bo = (const float*)d_in[9];
    float* out = (float*)d_out;

    __half *xh, *xl, *wf, *qf, *kf, *vf;
    cudaGetSymbolAddress((void**)&xh, g_xh);
    cudaGetSymbolAddress((void**)&xl, g_xl);
    cudaGetSymbolAddress((void**)&wf, g_w);
    cudaGetSymbolAddress((void**)&qf, g_q);
    cudaGetSymbolAddress((void**)&kf, g_k);
    cudaGetSymbolAddress((void**)&vf, g_v);

    const size_t WSZ = (size_t)D_ * D_;
    const int xn4 = (M_ * D_) / 4;
    const int wn4 = (D_ * D_) / 4;

    split_kernel<<<(xn4 + 255)/256, 256>>>(hidden, mask, xh, xl, xn4, 1);
    split4_kernel<<<dim3((wn4 + 255)/256, 4), 256>>>(Wq, Wk, Wv, Wo, wf, wn4);

    const int gsmem = 2 * G_STAGE * (int)sizeof(__half);   // 110592
    cudaFuncSetAttribute(mgemm_qkv_kernel, cudaFuncAttributeMaxDynamicSharedMemorySize, gsmem);
    cudaFuncSetAttribute(mgemm_o_kernel,   cudaFuncAttributeMaxDynamicSharedMemorySize, gsmem);

    mgemm_qkv_kernel<<<dim3(24, M_/128), 256, gsmem>>>(
        xh, xl, wf, bq, bk, bv, qf, kf, vf);

    const int asmem = 3 * A_STAGE_B;   // 56064
    cudaFuncSetAttribute(mattn_kernel, cudaFuncAttributeMaxDynamicSharedMemorySize, asmem);
    mattn_kernel<<<dim3(S_/128, B_*H_), 256, asmem>>>(mask);

    mgemm_o_kernel<<<dim3(D_/128, M_/128), 256, gsmem>>>(
        xh, xl, wf + 3*WSZ, bo, mask, out);
}

// round 14
// speedup vs baseline: 2.2558x; 1.2117x over previous
#include <cuda_runtime.h>
#include <cuda_bf16.h>
#include <cuda_fp16.h>
#include <math.h>
#include <stdint.h>

#define B_  4
#define S_  2048
#define D_  1024
#define H_  16
#define HD_ 64
#define M_  (B_*S_)

// ---------------- scratch ----------------
__device__ __half g_xh[(size_t)M_*D_];   // activations hi (hidden, then ctx)
__device__ __half g_xl[(size_t)M_*D_];   // activations lo (used by O-proj only)
__device__ __half g_w[(size_t)4*D_*D_];  // weights, single fp16
__device__ __half g_q[(size_t)M_*D_];    // pre-scaled by 0.125
__device__ __half g_k[(size_t)M_*D_];
__device__ __half g_v[(size_t)M_*D_];

// ---------------- asm helpers ----------------
__device__ __forceinline__ uint32_t smem_u32(const void* p) {
    uint32_t a;
    asm("{ .reg .u64 t; cvta.to.shared.u64 t, %1; cvt.u32.u64 %0, t; }" : "=r"(a) : "l"(p));
    return a;
}
#define CP_ASYNC16(dst, src) \
    asm volatile("cp.async.cg.shared.global [%0], [%1], 16;" :: "r"(dst), "l"(src))
#define CP_COMMIT() asm volatile("cp.async.commit_group;" ::: "memory")
#define CP_WAIT(n)  asm volatile("cp.async.wait_group %0;" :: "n"(n) : "memory")

#define MMA_F16(c, a, b0, b1) \
    asm volatile("mma.sync.aligned.m16n8k16.row.col.f32.f16.f16.f32 " \
        "{%0,%1,%2,%3}, {%4,%5,%6,%7}, {%8,%9}, {%0,%1,%2,%3};" \
        : "+f"((c)[0]), "+f"((c)[1]), "+f"((c)[2]), "+f"((c)[3]) \
        : "r"((a)[0]), "r"((a)[1]), "r"((a)[2]), "r"((a)[3]), "r"(b0), "r"(b1))

#define LDSM_X4(r0,r1,r2,r3, a) \
    asm volatile("ldmatrix.sync.aligned.m8n8.x4.shared.b16 {%0,%1,%2,%3}, [%4];" \
        : "=r"(r0), "=r"(r1), "=r"(r2), "=r"(r3) : "r"(a))

#define LDSM_X4_T(r0,r1,r2,r3, a) \
    asm volatile("ldmatrix.sync.aligned.m8n8.x4.trans.shared.b16 {%0,%1,%2,%3}, [%4];" \
        : "=r"(r0), "=r"(r1), "=r"(r2), "=r"(r3) : "r"(a))

__device__ __forceinline__ uint32_t pack_f16(float lo, float hi) {
    __half2 t = __floats2half2_rn(lo, hi);
    return *reinterpret_cast<uint32_t*>(&t);
}

// ---------------- fp32 -> fp16 hi/lo split (activations) ----------------
__global__ void split_kernel(const float* __restrict__ in, const int* __restrict__ mask,
                             __half* __restrict__ hi, __half* __restrict__ lo,
                             int n4, int use_mask)
{
    int i = blockIdx.x * blockDim.x + threadIdx.x;
    if (i >= n4) return;
    float4 v = reinterpret_cast<const float4*>(in)[i];
    if (use_mask) {
        float mv = (float)mask[i >> 8];
        v.x *= mv; v.y *= mv; v.z *= mv; v.w *= mv;
    }
    __half h0 = __float2half(v.x);
    __half h1 = __float2half(v.y);
    __half h2 = __float2half(v.z);
    __half h3 = __float2half(v.w);
    __half2 hh0; hh0.x = h0; hh0.y = h1;
    __half2 hh1; hh1.x = h2; hh1.y = h3;
    __half2 ll0, ll1;
    ll0.x = __float2half(v.x - __half2float(h0));
    ll0.y = __float2half(v.y - __half2float(h1));
    ll1.x = __float2half(v.z - __half2float(h2));
    ll1.y = __float2half(v.w - __half2float(h3));
    reinterpret_cast<__half2*>(hi)[2*i]   = hh0;
    reinterpret_cast<__half2*>(hi)[2*i+1] = hh1;
    reinterpret_cast<__half2*>(lo)[2*i]   = ll0;
    reinterpret_cast<__half2*>(lo)[2*i+1] = ll1;
}

// merged weight convert: single fp16, grid.y selects which W
__global__ void split4_kernel(const float* __restrict__ W0, const float* __restrict__ W1,
                              const float* __restrict__ W2, const float* __restrict__ W3,
                              __half* __restrict__ wout, int n4)
{
    int i = blockIdx.x * blockDim.x + threadIdx.x;
    if (i >= n4) return;
    const int w = blockIdx.y;
    const float* in = (w == 0) ? W0 : (w == 1) ? W1 : (w == 2) ? W2 : W3;
    const size_t off = (size_t)w * n4;
    float4 v = reinterpret_cast<const float4*>(in)[i];
    __half2 a; a.x = __float2half(v.x); a.y = __float2half(v.y);
    __half2 b; b.x = __float2half(v.z); b.y = __float2half(v.w);
    reinterpret_cast<__half2*>(wout)[2*(off + i)]     = a;
    reinterpret_cast<__half2*>(wout)[2*(off + i) + 1] = b;
}

#define GS_A  72

// ---------------- 1-pass fp16 QKV GEMM: C = Ah @ W^T + bias ----------------
#define G1_STAGE (2*128*GS_A)    // fp16 elems per stage (Ah, W tiles)

__device__ __forceinline__ void gemm1_issue(const __half* const srcs[2], __half* stage,
                                            int chunk, int tid)
{
#pragma unroll
    for (int it = 0; it < 8; it++) {
        int unit = tid + it*256;            // 0..2047
        int mat = unit >> 10, rem = unit & 1023;
        int row = rem >> 3,  g  = rem & 7;
        const __half* src = srcs[mat] + (size_t)row*D_ + chunk*64 + g*8;
        uint32_t dst = smem_u32(stage + mat*128*GS_A + row*GS_A + g*8);
        CP_ASYNC16(dst, src);
    }
}

__global__ void __launch_bounds__(256, 2) mgemm_qkv_kernel(
    const __half* __restrict__ Ah, const __half* __restrict__ W,
    const float* __restrict__ bq, const float* __restrict__ bk, const float* __restrict__ bv,
    __half* __restrict__ qf, __half* __restrict__ kf, __half* __restrict__ vf)
{
    extern __shared__ char smraw[];
    __shared__ float sbias[128];
    const int tid = threadIdx.x;
    const int lane = tid & 31;
    const int wid = tid >> 5;
    const int wr = wid >> 1;
    const int wc = wid & 1;
    const int proj = blockIdx.x >> 3;
    const int n0 = (blockIdx.x & 7) * 128;
    const int m0 = blockIdx.y * 128;
    const size_t WSZ = (size_t)D_ * D_;

    const float* bias = (proj == 0) ? bq : (proj == 1) ? bk : bv;
    __half* C = (proj == 0) ? qf : (proj == 1) ? kf : vf;
    const float qscale = (proj == 0) ? 0.125f : 1.0f;   // fold softmax scale into Q (exact pow2)
    if (tid < 128) sbias[tid] = bias[n0 + tid];

    __half* stg[2] = { (__half*)smraw, (__half*)smraw + G1_STAGE };

    float acc[2][8][4];
#pragma unroll
    for (int mt = 0; mt < 2; mt++)
#pragma unroll
        for (int n = 0; n < 8; n++)
#pragma unroll
            for (int c = 0; c < 4; c++) acc[mt][n][c] = 0.0f;

    const __half* srcs[2] = { Ah + (size_t)m0*D_, W + proj*WSZ + (size_t)n0*D_ };

    gemm1_issue(srcs, stg[0], 0, tid); CP_COMMIT();

    const int rowA = wr*32 + ((lane >> 3) & 1)*8 + (lane & 7);
    const int colA = (lane >> 4)*8;
    const int rowB = wc*64 + (lane >> 4)*8 + (lane & 7);
    const int colB = ((lane >> 3) & 1)*8;

    for (int chunk = 0; chunk < 16; chunk++) {
        CP_WAIT(0);
        __syncthreads();
        if (chunk + 1 < 16) {
            gemm1_issue(srcs, stg[(chunk + 1) & 1], chunk + 1, tid);
            CP_COMMIT();
        }

        __half* As = stg[chunk & 1];
        __half* Ws = As + 128*GS_A;

#pragma unroll
        for (int kk = 0; kk < 4; kk++) {
            uint32_t ah[2][4];
#pragma unroll
            for (int mt = 0; mt < 2; mt++) {
                uint32_t a = smem_u32(As + (rowA + mt*16)*GS_A + kk*16 + colA);
                LDSM_X4(ah[mt][0], ah[mt][1], ah[mt][2], ah[mt][3], a);
            }
#pragma unroll
            for (int n4 = 0; n4 < 4; n4++) {
                uint32_t w0, w1, w2, w3;
                uint32_t a = smem_u32(Ws + (rowB + n4*16)*GS_A + kk*16 + colB);
                LDSM_X4(w0, w1, w2, w3, a);
#pragma unroll
                for (int mt = 0; mt < 2; mt++) {
                    MMA_F16(acc[mt][2*n4],   ah[mt], w0, w1);
                    MMA_F16(acc[mt][2*n4+1], ah[mt], w2, w3);
                }
            }
        }
    }

    const int cb = (lane & 3)*2;
    const int e_loc = wc*64 + cb;
    const int h = (n0 + wc*64) >> 6;
#pragma unroll
    for (int mt = 0; mt < 2; mt++) {
#pragma unroll
        for (int half = 0; half < 2; half++) {
            const int m = m0 + wr*32 + mt*16 + half*8 + (lane >> 2);
            const int b = m >> 11, s = m & 2047;
            const size_t base = (((size_t)(b*H_ + h))*S_ + s)*HD_;
#pragma unroll
            for (int n = 0; n < 8; n++) {
                float v0 = (acc[mt][n][half*2]     + sbias[e_loc + n*8])     * qscale;
                float v1 = (acc[mt][n][half*2 + 1] + sbias[e_loc + n*8 + 1]) * qscale;
                *reinterpret_cast<uint32_t*>(C + base + n*8 + cb) = pack_f16(v0, v1);
            }
        }
    }
}

// ---------------- 2-pass fp16 O-proj GEMM (unchanged) ----------------
#define G_STAGE (3*128*GS_A)

__device__ __forceinline__ void gemm_issue(const __half* const srcs[3], __half* stage,
                                           int chunk, int tid)
{
#pragma unroll
    for (int it = 0; it < 12; it++) {
        int unit = tid + it*256;
        int mat = unit >> 10, rem = unit & 1023;
        int row = rem >> 3,  g  = rem & 7;
        const __half* src = srcs[mat] + (size_t)row*D_ + chunk*64 + g*8;
        uint32_t dst = smem_u32(stage + mat*128*GS_A + row*GS_A + g*8);
        CP_ASYNC16(dst, src);
    }
}

__global__ void __launch_bounds__(256, 2) mgemm_o_kernel(
    const __half* __restrict__ Ah, const __half* __restrict__ Al,
    const __half* __restrict__ W,
    const float* __restrict__ bias, const int* __restrict__ mask,
    float* __restrict__ Cf)
{
    extern __shared__ char smraw[];
    __shared__ float sbias[128];
    const int tid = threadIdx.x;
    const int lane = tid & 31;
    const int wid = tid >> 5;
    const int wr = wid >> 1;
    const int wc = wid & 1;
    const int m0 = blockIdx.y * 128;
    const int n0 = blockIdx.x * 128;
    if (tid < 128) sbias[tid] = bias[n0 + tid];

    __half* stg[2] = { (__half*)smraw, (__half*)smraw + G_STAGE };

    float acc[2][8][4];
#pragma unroll
    for (int mt = 0; mt < 2; mt++)
#pragma unroll
        for (int n = 0; n < 8; n++)
#pragma unroll
            for (int c = 0; c < 4; c++) acc[mt][n][c] = 0.0f;

    const __half* srcs[3] = { Ah + (size_t)m0*D_, Al + (size_t)m0*D_,
                              W  + (size_t)n0*D_ };

    gemm_issue(srcs, stg[0], 0, tid); CP_COMMIT();

    const int rowA = wr*32 + ((lane >> 3) & 1)*8 + (lane & 7);
    const int colA = (lane >> 4)*8;
    const int rowB = wc*64 + (lane >> 4)*8 + (lane & 7);
    const int colB = ((lane >> 3) & 1)*8;

    for (int chunk = 0; chunk < 16; chunk++) {
        CP_WAIT(0);
        __syncthreads();
        if (chunk + 1 < 16) {
            gemm_issue(srcs, stg[(chunk + 1) & 1], chunk + 1, tid);
            CP_COMMIT();
        }

        __half* As_h = stg[chunk & 1];
        __half* As_l = As_h + 128*GS_A;
        __half* Ws   = As_l + 128*GS_A;

#pragma unroll
        for (int kk = 0; kk < 4; kk++) {
            uint32_t ah[2][4], al[2][4];
#pragma unroll
            for (int mt = 0; mt < 2; mt++) {
                uint32_t a = smem_u32(As_h + (rowA + mt*16)*GS_A + kk*16 + colA);
                LDSM_X4(ah[mt][0], ah[mt][1], ah[mt][2], ah[mt][3], a);
                a = smem_u32(As_l + (rowA + mt*16)*GS_A + kk*16 + colA);
                LDSM_X4(al[mt][0], al[mt][1], al[mt][2], al[mt][3], a);
            }
#pragma unroll
            for (int n4 = 0; n4 < 4; n4++) {
                uint32_t w0, w1, w2, w3;
                uint32_t a = smem_u32(Ws + (rowB + n4*16)*GS_A + kk*16 + colB);
                LDSM_X4(w0, w1, w2, w3, a);
#pragma unroll
                for (int mt = 0; mt < 2; mt++) {
                    MMA_F16(acc[mt][2*n4],   ah[mt], w0, w1);
                    MMA_F16(acc[mt][2*n4],   al[mt], w0, w1);
                    MMA_F16(acc[mt][2*n4+1], ah[mt], w2, w3);
                    MMA_F16(acc[mt][2*n4+1], al[mt], w2, w3);
                }
            }
        }
    }

    const int cb = (lane & 3)*2;
    const int e_loc = wc*64 + cb;
#pragma unroll
    for (int mt = 0; mt < 2; mt++) {
#pragma unroll
        for (int half = 0; half < 2; half++) {
            const int m = m0 + wr*32 + mt*16 + half*8 + (lane >> 2);
            const float maskv = (float)mask[m];
            float* outp = Cf + (size_t)m*D_ + n0;
#pragma unroll
            for (int n = 0; n < 8; n++) {
                float2 v;
                v.x = (acc[mt][n][half*2]     + sbias[e_loc + n*8])     * maskv;
                v.y = (acc[mt][n][half*2 + 1] + sbias[e_loc + n*8 + 1]) * maskv;
                *reinterpret_cast<float2*>(outp + e_loc + n*8) = v;
            }
        }
    }
}

// ---------------- fp16 1-pass attention (scale pre-folded into Q) ----------------
#define AS_B 72
#define A_KTILE (64*AS_B)
#define A_TILES_B (2*A_KTILE*2)           // K+V bytes = 18432
#define A_STAGE_B (A_TILES_B + 256)       // + mask slot = 18688
#define A_QTILE (128*AS_B)

__device__ __forceinline__ void attn_issue(const __half* kf, const __half* vf,
                                           const int* __restrict__ maskp,
                                           char* stage, int kb, int tid)
{
    __half* st = (__half*)stage;
#pragma unroll
    for (int it = 0; it < 2; it++) {
        int unit = tid + it*256;
        int row = unit >> 3, g = unit & 7;
        const size_t go = (size_t)(kb + row)*HD_ + g*8;
        const int so = row*AS_B + g*8;
        CP_ASYNC16(smem_u32(st + so), kf + go);
        CP_ASYNC16(smem_u32(st + A_KTILE + so), vf + go);
    }
    if (tid < 16)
        CP_ASYNC16(smem_u32(stage + A_TILES_B + tid*16), maskp + kb + tid*4);
}

__global__ void __launch_bounds__(256, 2) mattn_kernel(const int* __restrict__ mask)
{
    extern __shared__ char smraw[];
    char* stg[3] = { smraw, smraw + A_STAGE_B, smraw + 2*A_STAGE_B };
    __half* Qs = (__half*)stg[2];   // Q aliases stage 2

    const int tid  = threadIdx.x;
    const int lane = tid & 31;
    const int ti   = tid >> 5;
    const int bh = blockIdx.y;
    const int b  = bh >> 4, h = bh & 15;
    const int q0 = blockIdx.x << 7;

    const __half* Kg = g_k + (size_t)bh*S_*HD_;
    const __half* Vg = g_v + (size_t)bh*S_*HD_;
    const int* maskp = mask + b*S_;

    attn_issue(Kg, Vg, maskp, stg[0], 0,  tid); CP_COMMIT();
    attn_issue(Kg, Vg, maskp, stg[1], 64, tid); CP_COMMIT();

    const __half* Qg = g_q + ((size_t)bh*S_ + q0)*HD_;
#pragma unroll
    for (int it = 0; it < 2; it++) {
        int unit = tid + it*256;
        int row = unit >> 3, c8 = unit & 7;
        *reinterpret_cast<uint4*>(Qs + row*AS_B + c8*8) =
            *reinterpret_cast<const uint4*>(Qg + (size_t)row*HD_ + c8*8);
        int row2 = row + 64;
        *reinterpret_cast<uint4*>(Qs + row2*AS_B + c8*8) =
            *reinterpret_cast<const uint4*>(Qg + (size_t)row2*HD_ + c8*8);
    }
    __syncthreads();

    uint32_t qf[4][4];
    {
        const int rowQ = ti*16 + ((lane >> 3) & 1)*8 + (lane & 7);
        const int colQ = (lane >> 4)*8;
#pragma unroll
        for (int g = 0; g < 4; g++) {
            uint32_t a = smem_u32(Qs + rowQ*AS_B + g*16 + colQ);
            LDSM_X4(qf[g][0], qf[g][1], qf[g][2], qf[g][3], a);
        }
    }
    __syncthreads();

    float oc[8][4];
#pragma unroll
    for (int n = 0; n < 8; n++)
#pragma unroll
        for (int c = 0; c < 4; c++) oc[n][c] = 0.0f;
    float lp0 = 0.0f, lp1 = 0.0f;

    const int rowK = (lane >> 4)*8 + (lane & 7);
    const int colK = ((lane >> 3) & 1)*8;
    const int rowV = ((lane >> 3) & 1)*8 + (lane & 7);
    const int colV = (lane >> 4)*8;
    const int cb   = (lane & 3)*2;

    for (int kt = 0; kt < 32; kt++) {
        if (kt < 31) { CP_WAIT(1); } else { CP_WAIT(0); }
        __syncthreads();
        if (kt + 2 < 32) {
            attn_issue(Kg, Vg, maskp, stg[(kt + 2) % 3], (kt + 2) << 6, tid);
            CP_COMMIT();
        }

        char* st = stg[kt % 3];
        __half* Kf = (__half*)st;
        __half* Vf = Kf + A_KTILE;
        const int* kmi = (const int*)(st + A_TILES_B);

        float sc[8][4];
#pragma unroll
        for (int n = 0; n < 8; n++)
#pragma unroll
            for (int c = 0; c < 4; c++) sc[n][c] = 0.0f;

#pragma unroll
        for (int g = 0; g < 4; g++) {
#pragma unroll
            for (int n2 = 0; n2 < 4; n2++) {
                uint32_t k0, k1, k2, k3;
                uint32_t a = smem_u32(Kf + (n2*16 + rowK)*AS_B + g*16 + colK);
                LDSM_X4(k0, k1, k2, k3, a);
                MMA_F16(sc[2*n2],   qf[g], k0, k1);
                MMA_F16(sc[2*n2+1], qf[g], k2, k3);
            }
        }

        // scores already carry the 0.125 scale (folded into Q)
#pragma unroll
        for (int n = 0; n < 8; n++) {
            const int colb = n*8 + cb;
            const float km0 = (float)kmi[colb];
            const float km1 = (float)kmi[colb + 1];
            float p0 = __expf(sc[n][0]) * km0;
            float p1 = __expf(sc[n][1]) * km1;
            float p2 = __expf(sc[n][2]) * km0;
            float p3 = __expf(sc[n][3]) * km1;
            lp0 += p0 + p1;
            lp1 += p2 + p3;
            sc[n][0] = p0; sc[n][1] = p1; sc[n][2] = p2; sc[n][3] = p3;
        }

#pragma unroll
        for (int g = 0; g < 4; g++) {
            uint32_t pf[4];
#pragma unroll
            for (int nn = 0; nn < 2; nn++) {
                const int n = 2*g + nn;
                pf[nn*2]     = pack_f16(sc[n][0], sc[n][1]);
                pf[nn*2 + 1] = pack_f16(sc[n][2], sc[n][3]);
            }
#pragma unroll
            for (int d2 = 0; d2 < 4; d2++) {
                uint32_t v0, v1, v2, v3;
                uint32_t a = smem_u32(Vf + (g*16 + rowV)*AS_B + d2*16 + colV);
                LDSM_X4_T(v0, v1, v2, v3, a);
                MMA_F16(oc[2*d2],   pf, v0, v1);
                MMA_F16(oc[2*d2+1], pf, v2, v3);
            }
        }
    }

    lp0 += __shfl_xor_sync(0xffffffffu, lp0, 1);
    lp0 += __shfl_xor_sync(0xffffffffu, lp0, 2);
    lp1 += __shfl_xor_sync(0xffffffffu, lp1, 1);
    lp1 += __shfl_xor_sync(0xffffffffu, lp1, 2);
    const float inv0 = (lp0 > 0.f) ? (1.0f / lp0) : 0.f;
    const float inv1 = (lp1 > 0.f) ? (1.0f / lp1) : 0.f;

    // ctx written as fp16 hi/lo (O-projection consumes 2-pass)
    const int row0 = q0 + ti*16 + (lane >> 2);
    const size_t base0 = ((size_t)(b*S_ + row0))*D_ + h*HD_ + cb;
    const size_t base1 = base0 + 8*(size_t)D_;
#pragma unroll
    for (int n = 0; n < 8; n++) {
        float v00 = oc[n][0]*inv0, v01 = oc[n][1]*inv0;
        float v10 = oc[n][2]*inv1, v11 = oc[n][3]*inv1;
        __half h00 = __float2half(v00), h01 = __float2half(v01);
        __half h10 = __float2half(v10), h11 = __float2half(v11);
        __half2 a0; a0.x = h00; a0.y = h01;
        __half2 a1; a1.x = h10; a1.y = h11;
        *reinterpret_cast<__half2*>(g_xh + base0 + n*8) = a0;
        *reinterpret_cast<__half2*>(g_xh + base1 + n*8) = a1;
        *reinterpret_cast<uint32_t*>(g_xl + base0 + n*8) =
            pack_f16(v00 - __half2float(h00), v01 - __half2float(h01));
        *reinterpret_cast<uint32_t*>(g_xl + base1 + n*8) =
            pack_f16(v10 - __half2float(h10), v11 - __half2float(h11));
    }
}

// ---------------- launch ----------------
extern "C" void kernel_launch(void* const* d_in, const int* in_sizes, int n_in,
                              void* d_out, int out_size)
{
    const float* hidden = (const float*)d_in[0];
    const int*   mask   = (const int*)d_in[1];
    const float* Wq = (const float*)d_in[2];
    const float* bq = (const float*)d_in[3];
    const float* Wk = (const float*)d_in[4];
    const float* bk = (const float*)d_in[5];
    const float* Wv = (const float*)d_in[6];
    const float* bv = (const float*)d_in[7];
    const float* Wo = (const float*)d_in[8];
    const float* bo = (const float*)d_in[9];
    float* out = (float*)d_out;

    __half *xh, *xl, *wf, *qf, *kf, *vf;
    cudaGetSymbolAddress((void**)&xh, g_xh);
    cudaGetSymbolAddress((void**)&xl, g_xl);
    cudaGetSymbolAddress((void**)&wf, g_w);
    cudaGetSymbolAddress((void**)&qf, g_q);
    cudaGetSymbolAddress((void**)&kf, g_k);
    cudaGetSymbolAddress((void**)&vf, g_v);

    const size_t WSZ = (size_t)D_ * D_;
    const int xn4 = (M_ * D_) / 4;
    const int wn4 = (D_ * D_) / 4;

    split_kernel<<<(xn4 + 255)/256, 256>>>(hidden, mask, xh, xl, xn4, 1);
    split4_kernel<<<dim3((wn4 + 255)/256, 4), 256>>>(Wq, Wk, Wv, Wo, wf, wn4);

    const int g1smem = 2 * G1_STAGE * (int)sizeof(__half);   // 73728
    const int gsmem  = 2 * G_STAGE  * (int)sizeof(__half);   // 110592
    cudaFuncSetAttribute(mgemm_qkv_kernel, cudaFuncAttributeMaxDynamicSharedMemorySize, g1smem);
    cudaFuncSetAttribute(mgemm_o_kernel,   cudaFuncAttributeMaxDynamicSharedMemorySize, gsmem);

    mgemm_qkv_kernel<<<dim3(24, M_/128), 256, g1smem>>>(
        xh, wf, bq, bk, bv, qf, kf, vf);

    const int asmem = 3 * A_STAGE_B;   // 56064
    cudaFuncSetAttribute(mattn_kernel, cudaFuncAttributeMaxDynamicSharedMemorySize, asmem);
    mattn_kernel<<<dim3(S_/128, B_*H_), 256, asmem>>>(mask);

    mgemm_o_kernel<<<dim3(D_/128, M_/128), 256, gsmem>>>(
        xh, xl, wf + 3*WSZ, bo, mask, out);
}

// round 15
// speedup vs baseline: 2.7171x; 1.2045x over previous
#include <cuda_runtime.h>
#include <cuda_fp16.h>
#include <math.h>
#include <stdint.h>

#define B_  4
#define S_  2048
#define D_  1024
#define H_  16
#define HD_ 64
#define M_  (B_*S_)

// ---------------- scratch ----------------
__device__ __half g_x[(size_t)M_*D_];    // activations fp16 (hidden, then ctx)
__device__ __half g_w[(size_t)4*D_*D_];  // weights fp16
__device__ __half g_q[(size_t)M_*D_];    // pre-scaled by 0.125*log2(e)
__device__ __half g_k[(size_t)M_*D_];
__device__ __half g_v[(size_t)M_*D_];
__device__ float  g_moff[(size_t)M_];    // additive key-mask: 0 or -1e5

// ---------------- asm helpers ----------------
__device__ __forceinline__ uint32_t smem_u32(const void* p) {
    uint32_t a;
    asm("{ .reg .u64 t; cvta.to.shared.u64 t, %1; cvt.u32.u64 %0, t; }" : "=r"(a) : "l"(p));
    return a;
}
#define CP_ASYNC16(dst, src) \
    asm volatile("cp.async.cg.shared.global [%0], [%1], 16;" :: "r"(dst), "l"(src))
#define CP_COMMIT() asm volatile("cp.async.commit_group;" ::: "memory")
#define CP_WAIT(n)  asm volatile("cp.async.wait_group %0;" :: "n"(n) : "memory")

#define MMA_F16(c, a, b0, b1) \
    asm volatile("mma.sync.aligned.m16n8k16.row.col.f32.f16.f16.f32 " \
        "{%0,%1,%2,%3}, {%4,%5,%6,%7}, {%8,%9}, {%0,%1,%2,%3};" \
        : "+f"((c)[0]), "+f"((c)[1]), "+f"((c)[2]), "+f"((c)[3]) \
        : "r"((a)[0]), "r"((a)[1]), "r"((a)[2]), "r"((a)[3]), "r"(b0), "r"(b1))

#define LDSM_X4(r0,r1,r2,r3, a) \
    asm volatile("ldmatrix.sync.aligned.m8n8.x4.shared.b16 {%0,%1,%2,%3}, [%4];" \
        : "=r"(r0), "=r"(r1), "=r"(r2), "=r"(r3) : "r"(a))

#define LDSM_X4_T(r0,r1,r2,r3, a) \
    asm volatile("ldmatrix.sync.aligned.m8n8.x4.trans.shared.b16 {%0,%1,%2,%3}, [%4];" \
        : "=r"(r0), "=r"(r1), "=r"(r2), "=r"(r3) : "r"(a))

__device__ __forceinline__ uint32_t pack_f16(float lo, float hi) {
    __half2 t = __floats2half2_rn(lo, hi);
    return *reinterpret_cast<uint32_t*>(&t);
}
__device__ __forceinline__ float ex2f(float x) {
    float r;
    asm("ex2.approx.ftz.f32 %0, %1;" : "=f"(r) : "f"(x));
    return r;
}

// ---------------- fp32 -> fp16 convert (masked activations) ----------------
__global__ void conv_kernel(const float* __restrict__ in, const int* __restrict__ mask,
                            __half* __restrict__ out, int n4, int use_mask)
{
    int i = blockIdx.x * blockDim.x + threadIdx.x;
    if (i >= n4) return;
    float4 v = reinterpret_cast<const float4*>(in)[i];
    if (use_mask) {
        float mv = (float)mask[i >> 8];
        v.x *= mv; v.y *= mv; v.z *= mv; v.w *= mv;
    }
    __half2 a; a.x = __float2half(v.x); a.y = __float2half(v.y);
    __half2 b; b.x = __float2half(v.z); b.y = __float2half(v.w);
    reinterpret_cast<__half2*>(out)[2*i]     = a;
    reinterpret_cast<__half2*>(out)[2*i+1]   = b;
}

// merged weight convert: grid.y selects which W
__global__ void split4_kernel(const float* __restrict__ W0, const float* __restrict__ W1,
                              const float* __restrict__ W2, const float* __restrict__ W3,
                              __half* __restrict__ wout, int n4)
{
    int i = blockIdx.x * blockDim.x + threadIdx.x;
    if (i >= n4) return;
    const int w = blockIdx.y;
    const float* in = (w == 0) ? W0 : (w == 1) ? W1 : (w == 2) ? W2 : W3;
    const size_t off = (size_t)w * n4;
    float4 v = reinterpret_cast<const float4*>(in)[i];
    __half2 a; a.x = __float2half(v.x); a.y = __float2half(v.y);
    __half2 b; b.x = __float2half(v.z); b.y = __float2half(v.w);
    reinterpret_cast<__half2*>(wout)[2*(off + i)]     = a;
    reinterpret_cast<__half2*>(wout)[2*(off + i) + 1] = b;
}

// additive mask: 0 for kept keys, -1e5 for masked
__global__ void moff_kernel(const int* __restrict__ mask, float* __restrict__ moff, int n)
{
    int i = blockIdx.x * blockDim.x + threadIdx.x;
    if (i < n) moff[i] = mask[i] ? 0.0f : -1.0e5f;
}

#define GS_A  72
#define G1_STAGE (2*128*GS_A)    // fp16 elems per stage (A, W tiles)

// ---------------- 1-pass fp16 GEMM mainloop ----------------
__device__ __forceinline__ void gemm1_issue(const __half* const srcs[2], __half* stage,
                                            int chunk, int tid)
{
#pragma unroll
    for (int it = 0; it < 8; it++) {
        int unit = tid + it*256;            // 0..2047
        int mat = unit >> 10, rem = unit & 1023;
        int row = rem >> 3,  g  = rem & 7;
        const __half* src = srcs[mat] + (size_t)row*D_ + chunk*64 + g*8;
        uint32_t dst = smem_u32(stage + mat*128*GS_A + row*GS_A + g*8);
        CP_ASYNC16(dst, src);
    }
}

__device__ __forceinline__ void mgemm1_main(
    const __half* __restrict__ A, const __half* __restrict__ W,
    int m0, int n0, int tid, __half* stg0, float acc[2][8][4])
{
    __half* stg[2] = { stg0, stg0 + G1_STAGE };
    const int lane = tid & 31;
    const int wid = tid >> 5;
    const int wr = wid >> 1;
    const int wc = wid & 1;

#pragma unroll
    for (int mt = 0; mt < 2; mt++)
#pragma unroll
        for (int n = 0; n < 8; n++)
#pragma unroll
            for (int c = 0; c < 4; c++) acc[mt][n][c] = 0.0f;

    const __half* srcs[2] = { A + (size_t)m0*D_, W + (size_t)n0*D_ };

    gemm1_issue(srcs, stg[0], 0, tid); CP_COMMIT();

    const int rowA = wr*32 + ((lane >> 3) & 1)*8 + (lane & 7);
    const int colA = (lane >> 4)*8;
    const int rowB = wc*64 + (lane >> 4)*8 + (lane & 7);
    const int colB = ((lane >> 3) & 1)*8;

    for (int chunk = 0; chunk < 16; chunk++) {
        CP_WAIT(0);
        __syncthreads();
        if (chunk + 1 < 16) {
            gemm1_issue(srcs, stg[(chunk + 1) & 1], chunk + 1, tid);
            CP_COMMIT();
        }

        __half* As = stg[chunk & 1];
        __half* Ws = As + 128*GS_A;

#pragma unroll
        for (int kk = 0; kk < 4; kk++) {
            uint32_t ah[2][4];
#pragma unroll
            for (int mt = 0; mt < 2; mt++) {
                uint32_t a = smem_u32(As + (rowA + mt*16)*GS_A + kk*16 + colA);
                LDSM_X4(ah[mt][0], ah[mt][1], ah[mt][2], ah[mt][3], a);
            }
#pragma unroll
            for (int n4 = 0; n4 < 4; n4++) {
                uint32_t w0, w1, w2, w3;
                uint32_t a = smem_u32(Ws + (rowB + n4*16)*GS_A + kk*16 + colB);
                LDSM_X4(w0, w1, w2, w3, a);
#pragma unroll
                for (int mt = 0; mt < 2; mt++) {
                    MMA_F16(acc[mt][2*n4],   ah[mt], w0, w1);
                    MMA_F16(acc[mt][2*n4+1], ah[mt], w2, w3);
                }
            }
        }
    }
}

// merged QKV GEMM: grid.x = 24 (proj = bx>>3, ntile = bx&7)
__global__ void __launch_bounds__(256, 2) mgemm_qkv_kernel(
    const __half* __restrict__ A, const __half* __restrict__ W,
    const float* __restrict__ bq, const float* __restrict__ bk, const float* __restrict__ bv,
    __half* __restrict__ qf, __half* __restrict__ kf, __half* __restrict__ vf)
{
    extern __shared__ char smraw[];
    __shared__ float sbias[128];
    const int tid = threadIdx.x;
    const int lane = tid & 31;
    const int wid = tid >> 5;
    const int wr = wid >> 1;
    const int wc = wid & 1;
    const int proj = blockIdx.x >> 3;
    const int n0 = (blockIdx.x & 7) * 128;
    const int m0 = blockIdx.y * 128;
    const size_t WSZ = (size_t)D_ * D_;

    const float* bias = (proj == 0) ? bq : (proj == 1) ? bk : bv;
    __half* C = (proj == 0) ? qf : (proj == 1) ? kf : vf;
    // Q carries softmax scale AND log2(e) so attention can use raw ex2
    const float qscale = (proj == 0) ? 0.125f * 1.44269504088896f : 1.0f;
    if (tid < 128) sbias[tid] = bias[n0 + tid];

    float acc[2][8][4];
    mgemm1_main(A, W + proj*WSZ, m0, n0, tid, (__half*)smraw, acc);

    const int cb = (lane & 3)*2;
    const int e_loc = wc*64 + cb;
    const int h = (n0 + wc*64) >> 6;
#pragma unroll
    for (int mt = 0; mt < 2; mt++) {
#pragma unroll
        for (int half = 0; half < 2; half++) {
            const int m = m0 + wr*32 + mt*16 + half*8 + (lane >> 2);
            const int b = m >> 11, s = m & 2047;
            const size_t base = (((size_t)(b*H_ + h))*S_ + s)*HD_;
#pragma unroll
            for (int n = 0; n < 8; n++) {
                float v0 = (acc[mt][n][half*2]     + sbias[e_loc + n*8])     * qscale;
                float v1 = (acc[mt][n][half*2 + 1] + sbias[e_loc + n*8 + 1]) * qscale;
                *reinterpret_cast<uint32_t*>(C + base + n*8 + cb) = pack_f16(v0, v1);
            }
        }
    }
}

// 1-pass O-projection GEMM (fp32 out * rowmask)
__global__ void __launch_bounds__(256, 2) mgemm_o_kernel(
    const __half* __restrict__ A, const __half* __restrict__ W,
    const float* __restrict__ bias, const int* __restrict__ mask,
    float* __restrict__ Cf)
{
    extern __shared__ char smraw[];
    __shared__ float sbias[128];
    const int tid = threadIdx.x;
    const int lane = tid & 31;
    const int wid = tid >> 5;
    const int wr = wid >> 1;
    const int wc = wid & 1;
    const int m0 = blockIdx.y * 128;
    const int n0 = blockIdx.x * 128;
    if (tid < 128) sbias[tid] = bias[n0 + tid];

    float acc[2][8][4];
    mgemm1_main(A, W, m0, n0, tid, (__half*)smraw, acc);

    const int cb = (lane & 3)*2;
    const int e_loc = wc*64 + cb;
#pragma unroll
    for (int mt = 0; mt < 2; mt++) {
#pragma unroll
        for (int half = 0; half < 2; half++) {
            const int m = m0 + wr*32 + mt*16 + half*8 + (lane >> 2);
            const float maskv = (float)mask[m];
            float* outp = Cf + (size_t)m*D_ + n0;
#pragma unroll
            for (int n = 0; n < 8; n++) {
                float2 v;
                v.x = (acc[mt][n][half*2]     + sbias[e_loc + n*8])     * maskv;
                v.y = (acc[mt][n][half*2 + 1] + sbias[e_loc + n*8 + 1]) * maskv;
                *reinterpret_cast<float2*>(outp + e_loc + n*8) = v;
            }
        }
    }
}

// ---------------- fp16 attention: ex2 + additive mask, uint32 smem addressing ----------------
#define AS_B 72
#define A_KTILE (64*AS_B)                 // fp16 elems per 64x64 tile
#define A_KTILE_B (A_KTILE*2)             // bytes
#define A_TILES_B (2*A_KTILE_B)           // K+V bytes = 18432
#define A_STAGE_B (A_TILES_B + 256)       // + fp32 mask slot (64 floats) = 18688
#define A_QTILE (128*AS_B)

__device__ __forceinline__ void attn_issue(const __half* kf, const __half* vf,
                                           const float* __restrict__ moffp,
                                           uint32_t stage_u, int kb, int tid)
{
#pragma unroll
    for (int it = 0; it < 2; it++) {
        int unit = tid + it*256;
        int row = unit >> 3, g = unit & 7;
        const size_t go = (size_t)(kb + row)*HD_ + g*8;
        const uint32_t so = (uint32_t)(row*AS_B + g*8)*2;
        CP_ASYNC16(stage_u + so, kf + go);
        CP_ASYNC16(stage_u + A_KTILE_B + so, vf + go);
    }
    if (tid < 16)
        CP_ASYNC16(stage_u + A_TILES_B + tid*16, moffp + kb + tid*4);
}

__global__ void __launch_bounds__(256, 2) mattn_kernel(const int* __restrict__ mask)
{
    extern __shared__ char smraw[];
    const uint32_t sm_u = smem_u32(smraw);
    const uint32_t stu[3] = { sm_u, sm_u + A_STAGE_B, sm_u + 2*A_STAGE_B };
    __half* Qs = (__half*)(smraw + 2*A_STAGE_B);   // Q aliases stage 2

    const int tid  = threadIdx.x;
    const int lane = tid & 31;
    const int ti   = tid >> 5;
    const int bh = blockIdx.y;
    const int b  = bh >> 4, h = bh & 15;
    const int q0 = blockIdx.x << 7;

    const __half* Kg = g_k + (size_t)bh*S_*HD_;
    const __half* Vg = g_v + (size_t)bh*S_*HD_;
    const float* moffp = g_moff + b*S_;

    attn_issue(Kg, Vg, moffp, stu[0], 0,  tid); CP_COMMIT();
    attn_issue(Kg, Vg, moffp, stu[1], 64, tid); CP_COMMIT();

    const __half* Qg = g_q + ((size_t)bh*S_ + q0)*HD_;
#pragma unroll
    for (int it = 0; it < 2; it++) {
        int unit = tid + it*256;
        int row = unit >> 3, c8 = unit & 7;
        *reinterpret_cast<uint4*>(Qs + row*AS_B + c8*8) =
            *reinterpret_cast<const uint4*>(Qg + (size_t)row*HD_ + c8*8);
        int row2 = row + 64;
        *reinterpret_cast<uint4*>(Qs + row2*AS_B + c8*8) =
            *reinterpret_cast<const uint4*>(Qg + (size_t)row2*HD_ + c8*8);
    }
    __syncthreads();

    uint32_t qf[4][4];
    {
        const int rowQ = ti*16 + ((lane >> 3) & 1)*8 + (lane & 7);
        const int colQ = (lane >> 4)*8;
        const uint32_t qb = stu[2] + (uint32_t)(rowQ*AS_B + colQ)*2;
#pragma unroll
        for (int g = 0; g < 4; g++)
            LDSM_X4(qf[g][0], qf[g][1], qf[g][2], qf[g][3], qb + g*32);
    }
    __syncthreads();

    float oc[8][4];
#pragma unroll
    for (int n = 0; n < 8; n++)
#pragma unroll
        for (int c = 0; c < 4; c++) oc[n][c] = 0.0f;
    float lp0 = 0.0f, lp1 = 0.0f;

    // byte offsets for B-fragment ldmatrix
    const uint32_t offK = (uint32_t)(((lane >> 4)*8 + (lane & 7))*AS_B + ((lane >> 3) & 1)*8)*2;
    const uint32_t offV = (uint32_t)((((lane >> 3) & 1)*8 + (lane & 7))*AS_B + (lane >> 4)*8)*2;
    const int cb = (lane & 3)*2;

    for (int kt = 0; kt < 32; kt++) {
        if (kt < 31) { CP_WAIT(1); } else { CP_WAIT(0); }
        __syncthreads();
        if (kt + 2 < 32) {
            attn_issue(Kg, Vg, moffp, stu[(kt + 2) % 3], (kt + 2) << 6, tid);
            CP_COMMIT();
        }

        const uint32_t st_u = stu[kt % 3];
        const float* kmf = (const float*)(smraw + (st_u - sm_u) + A_TILES_B);

        // ---- S (log2-domain) = Q K^T ----
        float sc[8][4];
#pragma unroll
        for (int n = 0; n < 8; n++)
#pragma unroll
            for (int c = 0; c < 4; c++) sc[n][c] = 0.0f;

#pragma unroll
        for (int g = 0; g < 4; g++) {
#pragma unroll
            for (int n2 = 0; n2 < 4; n2++) {
                uint32_t k0, k1, k2, k3;
                LDSM_X4(k0, k1, k2, k3,
                        st_u + offK + (uint32_t)(n2*16*AS_B + g*16)*2);
                MMA_F16(sc[2*n2],   qf[g], k0, k1);
                MMA_F16(sc[2*n2+1], qf[g], k2, k3);
            }
        }

        // ---- P = ex2(s + moff): 1 MUFU per element, additive mask ----
#pragma unroll
        for (int n = 0; n < 8; n++) {
            const float2 mo = *reinterpret_cast<const float2*>(kmf + n*8 + cb);
            float p0 = ex2f(sc[n][0] + mo.x);
            float p1 = ex2f(sc[n][1] + mo.y);
            float p2 = ex2f(sc[n][2] + mo.x);
            float p3 = ex2f(sc[n][3] + mo.y);
            lp0 += p0 + p1;
            lp1 += p2 + p3;
            sc[n][0] = p0; sc[n][1] = p1; sc[n][2] = p2; sc[n][3] = p3;
        }

        // ---- pack P + PV ----
#pragma unroll
        for (int g = 0; g < 4; g++) {
            uint32_t pf[4];
#pragma unroll
            for (int nn = 0; nn < 2; nn++) {
                const int n = 2*g + nn;
                pf[nn*2]     = pack_f16(sc[n][0], sc[n][1]);
                pf[nn*2 + 1] = pack_f16(sc[n][2], sc[n][3]);
            }
#pragma unroll
            for (int d2 = 0; d2 < 4; d2++) {
                uint32_t v0, v1, v2, v3;
                LDSM_X4_T(v0, v1, v2, v3,
                          st_u + A_KTILE_B + offV + (uint32_t)(g*16*AS_B + d2*16)*2);
                MMA_F16(oc[2*d2],   pf, v0, v1);
                MMA_F16(oc[2*d2+1], pf, v2, v3);
            }
        }
    }

    lp0 += __shfl_xor_sync(0xffffffffu, lp0, 1);
    lp0 += __shfl_xor_sync(0xffffffffu, lp0, 2);
    lp1 += __shfl_xor_sync(0xffffffffu, lp1, 1);
    lp1 += __shfl_xor_sync(0xffffffffu, lp1, 2);
    const float inv0 = (lp0 > 0.f) ? (1.0f / lp0) : 0.f;
    const float inv1 = (lp1 > 0.f) ? (1.0f / lp1) : 0.f;

    // ctx written as single fp16 (O-projection is 1-pass)
    const int row0 = q0 + ti*16 + (lane >> 2);
    const size_t base0 = ((size_t)(b*S_ + row0))*D_ + h*HD_ + cb;
    const size_t base1 = base0 + 8*(size_t)D_;
#pragma unroll
    for (int n = 0; n < 8; n++) {
        *reinterpret_cast<uint32_t*>(g_x + base0 + n*8) =
            pack_f16(oc[n][0]*inv0, oc[n][1]*inv0);
        *reinterpret_cast<uint32_t*>(g_x + base1 + n*8) =
            pack_f16(oc[n][2]*inv1, oc[n][3]*inv1);
    }
}

// ---------------- launch ----------------
extern "C" void kernel_launch(void* const* d_in, const int* in_sizes, int n_in,
                              void* d_out, int out_size)
{
    const float* hidden = (const float*)d_in[0];
    const int*   mask   = (const int*)d_in[1];
    const float* Wq = (const float*)d_in[2];
    const float* bq = (const float*)d_in[3];
    const float* Wk = (const float*)d_in[4];
    const float* bk = (const float*)d_in[5];
    const float* Wv = (const float*)d_in[6];
    const float* bv = (const float*)d_in[7];
    const float* Wo = (const float*)d_in[8];
    const float* bo = (const float*)d_in[9];
    float* out = (float*)d_out;

    __half *xf, *wf, *qf, *kf, *vf;
    float* moff;
    cudaGetSymbolAddress((void**)&xf, g_x);
    cudaGetSymbolAddress((void**)&wf, g_w);
    cudaGetSymbolAddress((void**)&qf, g_q);
    cudaGetSymbolAddress((void**)&kf, g_k);
    cudaGetSymbolAddress((void**)&vf, g_v);
    cudaGetSymbolAddress((void**)&moff, g_moff);

    const size_t WSZ = (size_t)D_ * D_;
    const int xn4 = (M_ * D_) / 4;
    const int wn4 = (D_ * D_) / 4;

    conv_kernel<<<(xn4 + 255)/256, 256>>>(hidden, mask, xf, xn4, 1);
    split4_kernel<<<dim3((wn4 + 255)/256, 4), 256>>>(Wq, Wk, Wv, Wo, wf, wn4);
    moff_kernel<<<(M_ + 255)/256, 256>>>(mask, moff, M_);

    const int g1smem = 2 * G1_STAGE * (int)sizeof(__half);   // 73728
    cudaFuncSetAttribute(mgemm_qkv_kernel, cudaFuncAttributeMaxDynamicSharedMemorySize, g1smem);
    cudaFuncSetAttribute(mgemm_o_kernel,   cudaFuncAttributeMaxDynamicSharedMemorySize, g1smem);

    mgemm_qkv_kernel<<<dim3(24, M_/128), 256, g1smem>>>(
        xf, wf, bq, bk, bv, qf, kf, vf);

    const int asmem = 3 * A_STAGE_B;   // 56064
    cudaFuncSetAttribute(mattn_kernel, cudaFuncAttributeMaxDynamicSharedMemorySize, asmem);
    mattn_kernel<<<dim3(S_/128, B_*H_), 256, asmem>>>(mask);

    mgemm_o_kernel<<<dim3(D_/128, M_/128), 256, g1smem>>>(
        xf, wf + 3*WSZ, bo, mask, out);
}